// round 1
// baseline (speedup 1.0000x reference)
#include <cuda_runtime.h>

// ---------------- problem constants (fixed shapes from reference) ----------------
#define NBATCH   128
#define NM       100
#define NE       50
#define NS       25
#define NPB      175            // nodes per batch
#define NNODES   (NBATCH*NPB)   // 22400
#define HDIM     768
#define TDIM     256
#define DDIM     1024
#define OUTF     768
#define NLAYER   3
#define NEDGE    716800
#define LRELU    0.01f
#define LN_EPS   1e-5f

// ---------------- device scratch (static: no allocations allowed) ----------------
__device__ float g_x[(size_t)NNODES * DDIM];   // current features
__device__ float g_y[(size_t)NNODES * DDIM];   // aggregated features
__device__ int   g_deg_out[NNODES];
__device__ int   g_deg_in[NNODES];
__device__ float g_dinv_out[NNODES];
__device__ float g_dinv_in[NNODES];
__device__ int   g_offs[NNODES + 1];
__device__ int   g_cursor[NNODES];
__device__ int   g_col[NEDGE];                 // CSR by dst: src indices
__device__ float g_w[NEDGE];                   // per-edge weight dinv_out[s]*dinv_in[d]

// ---------------- small kernels ----------------
__global__ void zero_counters_kernel() {
    int i = blockIdx.x * blockDim.x + threadIdx.x;
    if (i < NNODES) {
        g_deg_out[i] = 0;
        g_deg_in[i]  = 0;
        g_cursor[i]  = 0;
    }
}

__global__ void degree_kernel(const int* __restrict__ esrc, const int* __restrict__ edst) {
    int e = blockIdx.x * blockDim.x + threadIdx.x;
    if (e < NEDGE) {
        atomicAdd(&g_deg_out[esrc[e]], 1);
        atomicAdd(&g_deg_in[edst[e]], 1);
    }
}

__global__ void dinv_kernel() {
    int i = blockIdx.x * blockDim.x + threadIdx.x;
    if (i < NNODES) {
        int dout = g_deg_out[i]; if (dout < 1) dout = 1;
        int din  = g_deg_in[i];  if (din  < 1) din  = 1;
        g_dinv_out[i] = rsqrtf((float)dout);
        g_dinv_in[i]  = rsqrtf((float)din);
    }
}

// single-block inclusive scan of g_deg_in -> g_offs (exclusive layout: offs[0]=0)
__global__ void scan_kernel() {
    __shared__ int warp_sums[32];
    __shared__ int s_carry;
    int t = threadIdx.x, lane = t & 31, wid = t >> 5;
    if (t == 0) { s_carry = 0; g_offs[0] = 0; }
    __syncthreads();
    for (int base = 0; base < NNODES; base += 1024) {
        int idx = base + t;
        int v = (idx < NNODES) ? g_deg_in[idx] : 0;
        int x = v;
        #pragma unroll
        for (int o = 1; o < 32; o <<= 1) {
            int y = __shfl_up_sync(0xFFFFFFFFu, x, o);
            if (lane >= o) x += y;
        }
        if (lane == 31) warp_sums[wid] = x;
        __syncthreads();
        if (wid == 0) {
            int ws = warp_sums[lane];
            #pragma unroll
            for (int o = 1; o < 32; o <<= 1) {
                int y = __shfl_up_sync(0xFFFFFFFFu, ws, o);
                if (lane >= o) ws += y;
            }
            warp_sums[lane] = ws;
        }
        __syncthreads();
        int add = s_carry + (wid > 0 ? warp_sums[wid - 1] : 0);
        int incl = x + add;
        if (idx < NNODES) g_offs[idx + 1] = incl;
        __syncthreads();
        if (t == 1023) s_carry = incl;
        __syncthreads();
    }
}

__global__ void fill_csr_kernel(const int* __restrict__ esrc, const int* __restrict__ edst) {
    int e = blockIdx.x * blockDim.x + threadIdx.x;
    if (e < NEDGE) {
        int s = esrc[e], d = edst[e];
        int pos = g_offs[d] + atomicAdd(&g_cursor[d], 1);
        g_col[pos] = s;
        g_w[pos] = g_dinv_out[s] * g_dinv_in[d];
    }
}

// ---------------- build node features + layernorm ----------------
__global__ void build_ln_kernel(const float* __restrict__ mhs,
                                const float* __restrict__ ehs,
                                const float* __restrict__ shs,
                                const float* __restrict__ temb,
                                const float* __restrict__ scale,
                                const float* __restrict__ bias) {
    int node = blockIdx.x;              // 0..NNODES-1
    int b = node / NPB;
    int i = node - b * NPB;
    int t = threadIdx.x;                // 256 threads, 4 floats each
    int c = t * 4;

    const float* src;
    int type;
    if (i < NM)          { type = 0; src = mhs + ((size_t)b * NM + i) * HDIM; }
    else if (i < NM+NE)  { type = 1; src = ehs + ((size_t)b * NE + (i - NM)) * HDIM; }
    else                 { type = 2; src = shs + ((size_t)b * NS + (i - NM - NE)) * HDIM; }

    float4 v;
    if (c < HDIM) v = *(const float4*)(src + c);
    else          v = *(const float4*)(temb + type * TDIM + (c - HDIM));

    float s1 = v.x + v.y + v.z + v.w;
    float s2 = v.x*v.x + v.y*v.y + v.z*v.z + v.w*v.w;

    // block reduce (8 warps)
    __shared__ float sh1[8], sh2[8], s_mu, s_r;
    int lane = t & 31, wid = t >> 5;
    #pragma unroll
    for (int o = 16; o > 0; o >>= 1) {
        s1 += __shfl_down_sync(0xFFFFFFFFu, s1, o);
        s2 += __shfl_down_sync(0xFFFFFFFFu, s2, o);
    }
    if (lane == 0) { sh1[wid] = s1; sh2[wid] = s2; }
    __syncthreads();
    if (wid == 0) {
        s1 = (lane < 8) ? sh1[lane] : 0.f;
        s2 = (lane < 8) ? sh2[lane] : 0.f;
        #pragma unroll
        for (int o = 4; o > 0; o >>= 1) {
            s1 += __shfl_down_sync(0xFFFFFFFFu, s1, o);
            s2 += __shfl_down_sync(0xFFFFFFFFu, s2, o);
        }
        if (lane == 0) {
            float mu = s1 / (float)DDIM;
            float var = s2 / (float)DDIM - mu * mu;
            s_mu = mu;
            s_r  = rsqrtf(var + LN_EPS);
        }
    }
    __syncthreads();
    float mu = s_mu, r = s_r;
    float4 sc = *(const float4*)(scale + c);
    float4 bi = *(const float4*)(bias + c);
    float4 o;
    o.x = (v.x - mu) * r * sc.x + bi.x;
    o.y = (v.y - mu) * r * sc.y + bi.y;
    o.z = (v.z - mu) * r * sc.z + bi.z;
    o.w = (v.w - mu) * r * sc.w + bi.w;
    *(float4*)(g_x + (size_t)node * DDIM + c) = o;
}

// ---------------- aggregation: g_y[d,:] = sum_e w_e * g_x[src_e,:] ----------------
__global__ void aggregate_kernel() {
    int node = blockIdx.x;
    int t = threadIdx.x;                 // 256 threads, one float4 column each
    int beg = g_offs[node], end = g_offs[node + 1];

    __shared__ int   s_col[256];
    __shared__ float s_w[256];
    const float4* x4 = (const float4*)g_x;

    float4 acc = make_float4(0.f, 0.f, 0.f, 0.f);
    for (int base = beg; base < end; base += 256) {
        int n = end - base; if (n > 256) n = 256;
        if (t < n) { s_col[t] = g_col[base + t]; s_w[t] = g_w[base + t]; }
        __syncthreads();
        for (int i = 0; i < n; i++) {
            float  ww = s_w[i];
            float4 v  = x4[(size_t)s_col[i] * 256 + t];
            acc.x += ww * v.x; acc.y += ww * v.y;
            acc.z += ww * v.z; acc.w += ww * v.w;
        }
        __syncthreads();
    }
    ((float4*)g_y)[(size_t)node * 256 + t] = acc;
}

// ---------------- SGEMM: C = act(A @ B + bias) ----------------
// 128x128 tile, BK=8, 256 threads, 8x8 microtile.
// mode 0: A = g_y, C = g_x            (layer GEMM, M=22400, N=K=1024)
// mode 1: A = g_x with entity row-map, C = Cext (final GEMM, M=6400, N=768, K=1024)
__global__ void __launch_bounds__(256)
sgemm_kernel(const float* __restrict__ B, const float* __restrict__ bias,
             float* __restrict__ Cext, int M, int N, int K, int mode, int relu) {
    __shared__ float As[8][128];
    __shared__ float Bs[8][128];

    const float* A = (mode == 0) ? g_y : g_x;
    float* C = (mode == 0) ? g_x : Cext;

    int tid  = threadIdx.x;
    int row0 = blockIdx.y * 128;
    int col0 = blockIdx.x * 128;

    int a_row = tid >> 1;
    int a_col = (tid & 1) * 4;
    int b_row = tid >> 5;
    int b_col = (tid & 31) * 4;

    int m_glob = row0 + a_row;
    size_t a_src_row;
    if (mode == 1) {
        int bb = m_glob / NE;           // batch
        int ii = m_glob - bb * NE;      // entity index
        a_src_row = (size_t)bb * NPB + NM + ii;
    } else {
        a_src_row = (size_t)m_glob;
    }
    const float* Aptr = A + a_src_row * K + a_col;
    const float* Bptr = B + (size_t)b_row * N + col0 + b_col;

    int ty = tid >> 4, tx = tid & 15;
    float acc[8][8];
    #pragma unroll
    for (int i = 0; i < 8; i++)
        #pragma unroll
        for (int j = 0; j < 8; j++) acc[i][j] = 0.f;

    for (int k0 = 0; k0 < K; k0 += 8) {
        float4 av = *(const float4*)(Aptr + k0);
        float4 bv = *(const float4*)(Bptr + (size_t)k0 * N);
        As[a_col + 0][a_row] = av.x;
        As[a_col + 1][a_row] = av.y;
        As[a_col + 2][a_row] = av.z;
        As[a_col + 3][a_row] = av.w;
        *(float4*)&Bs[b_row][b_col] = bv;
        __syncthreads();
        #pragma unroll
        for (int k = 0; k < 8; k++) {
            float a[8], b[8];
            #pragma unroll
            for (int i = 0; i < 8; i++) a[i] = As[k][ty * 8 + i];
            #pragma unroll
            for (int j = 0; j < 8; j++) b[j] = Bs[k][tx * 8 + j];
            #pragma unroll
            for (int i = 0; i < 8; i++)
                #pragma unroll
                for (int j = 0; j < 8; j++) acc[i][j] += a[i] * b[j];
        }
        __syncthreads();
    }

    #pragma unroll
    for (int i = 0; i < 8; i++) {
        int r = row0 + ty * 8 + i;
        #pragma unroll
        for (int j = 0; j < 8; j += 4) {
            int c = col0 + tx * 8 + j;
            float4 o;
            o.x = acc[i][j + 0] + bias[c + 0];
            o.y = acc[i][j + 1] + bias[c + 1];
            o.z = acc[i][j + 2] + bias[c + 2];
            o.w = acc[i][j + 3] + bias[c + 3];
            if (relu) {
                o.x = (o.x > 0.f) ? o.x : LRELU * o.x;
                o.y = (o.y > 0.f) ? o.y : LRELU * o.y;
                o.z = (o.z > 0.f) ? o.z : LRELU * o.z;
                o.w = (o.w > 0.f) ? o.w : LRELU * o.w;
            }
            *(float4*)&C[(size_t)r * N + c] = o;
        }
    }
}

// ---------------- launch ----------------
extern "C" void kernel_launch(void* const* d_in, const int* in_sizes, int n_in,
                              void* d_out, int out_size) {
    const float* mhs   = (const float*)d_in[0];
    const float* ehs   = (const float*)d_in[1];
    const float* shs   = (const float*)d_in[2];
    const int*   esrc  = (const int*)d_in[3];
    const int*   edst  = (const int*)d_in[4];
    const float* temb  = (const float*)d_in[5];
    const float* lns   = (const float*)d_in[6];
    const float* lnb   = (const float*)d_in[7];
    const float* gw    = (const float*)d_in[8];
    const float* gb    = (const float*)d_in[9];
    const float* fcw   = (const float*)d_in[10];
    const float* fcb   = (const float*)d_in[11];
    float* out = (float*)d_out;

    // graph preprocessing (once; reused by all 3 layers)
    zero_counters_kernel<<<(NNODES + 255) / 256, 256>>>();
    degree_kernel<<<(NEDGE + 255) / 256, 256>>>(esrc, edst);
    dinv_kernel<<<(NNODES + 255) / 256, 256>>>();
    scan_kernel<<<1, 1024>>>();
    fill_csr_kernel<<<(NEDGE + 255) / 256, 256>>>(esrc, edst);

    // features + layernorm -> g_x
    build_ln_kernel<<<NNODES, 256>>>(mhs, ehs, shs, temb, lns, lnb);

    // 3 GCN layers
    for (int l = 0; l < NLAYER; l++) {
        aggregate_kernel<<<NNODES, 256>>>();
        sgemm_kernel<<<dim3(DDIM / 128, NNODES / 128), 256>>>(
            gw + (size_t)l * DDIM * DDIM, gb + (size_t)l * DDIM,
            nullptr, NNODES, DDIM, DDIM, /*mode=*/0, /*relu=*/1);
    }

    // final fc on entity rows only: M = 128*50 = 6400, N = 768
    sgemm_kernel<<<dim3(OUTF / 128, (NBATCH * NE) / 128), 256>>>(
        fcw, fcb, out, NBATCH * NE, OUTF, DDIM, /*mode=*/1, /*relu=*/0);
}

// round 3
// speedup vs baseline: 1.9705x; 1.9705x over previous
#include <cuda_runtime.h>
#include <cuda_bf16.h>
#include <cstdint>

// ---------------- problem constants ----------------
#define NBATCH   128
#define NM       100
#define NE       50
#define NS       25
#define NPB      175
#define NNODES   (NBATCH*NPB)   // 22400
#define HDIM     768
#define TDIM     256
#define DDIM     1024
#define OUTF     768
#define NLAYER   3
#define NEDGE    716800
#define NENT     (NBATCH*NE)    // 6400
#define LRELU    0.01f
#define LN_EPS   1e-5f

// ---------------- device scratch ----------------
__device__ __align__(16) float          g_x[(size_t)NNODES * DDIM];
__device__ __align__(16) __nv_bfloat16  g_a_hi[(size_t)NNODES * DDIM];
__device__ __align__(16) __nv_bfloat16  g_a_lo[(size_t)NNODES * DDIM];
__device__ __align__(16) __nv_bfloat16  g_wt_hi[(size_t)NLAYER * DDIM * DDIM];
__device__ __align__(16) __nv_bfloat16  g_wt_lo[(size_t)NLAYER * DDIM * DDIM];
__device__ __align__(16) __nv_bfloat16  g_fcw_hi[(size_t)OUTF * DDIM];
__device__ __align__(16) __nv_bfloat16  g_fcw_lo[(size_t)OUTF * DDIM];
__device__ int   g_deg_out[NNODES];
__device__ int   g_deg_in[NNODES];
__device__ float g_dinv_out[NNODES];
__device__ float g_dinv_in[NNODES];
__device__ int   g_offs[NNODES + 1];
__device__ int   g_cursor[NNODES];
__device__ int   g_col[NEDGE];
__device__ float g_w[NEDGE];

// ---------------- helpers ----------------
__device__ __forceinline__ uint32_t smem_u32(const void* p) {
    uint32_t a;
    asm("{ .reg .u64 t; cvta.to.shared.u64 t, %1; cvt.u32.u64 %0, t; }" : "=r"(a) : "l"(p));
    return a;
}
#define LDSM4(r, addr) \
    asm volatile("ldmatrix.sync.aligned.m8n8.x4.shared.b16 {%0,%1,%2,%3}, [%4];" \
        : "=r"((r)[0]), "=r"((r)[1]), "=r"((r)[2]), "=r"((r)[3]) : "r"(addr))
#define LDSM2(r, addr) \
    asm volatile("ldmatrix.sync.aligned.m8n8.x2.shared.b16 {%0,%1}, [%2];" \
        : "=r"((r)[0]), "=r"((r)[1]) : "r"(addr))
#define MMA16816(d, a, b) \
    asm volatile("mma.sync.aligned.m16n8k16.row.col.f32.bf16.bf16.f32 " \
        "{%0,%1,%2,%3}, {%4,%5,%6,%7}, {%8,%9}, {%0,%1,%2,%3};" \
        : "+f"((d)[0]), "+f"((d)[1]), "+f"((d)[2]), "+f"((d)[3]) \
        : "r"((a)[0]), "r"((a)[1]), "r"((a)[2]), "r"((a)[3]), "r"((b)[0]), "r"((b)[1]))

__device__ __forceinline__ void split4_store(float4 v, __nv_bfloat16* hi, __nv_bfloat16* lo, size_t eidx) {
    __nv_bfloat16 h[4], l[4];
    float f[4] = {v.x, v.y, v.z, v.w};
#pragma unroll
    for (int k = 0; k < 4; k++) {
        h[k] = __float2bfloat16(f[k]);
        l[k] = __float2bfloat16(f[k] - __bfloat162float(h[k]));
    }
    *(uint2*)(hi + eidx) = *(uint2*)h;
    *(uint2*)(lo + eidx) = *(uint2*)l;
}

// ---------------- graph preprocessing ----------------
__global__ void zero_counters_kernel() {
    int i = blockIdx.x * blockDim.x + threadIdx.x;
    if (i < NNODES) { g_deg_out[i] = 0; g_deg_in[i] = 0; g_cursor[i] = 0; }
}
__global__ void degree_kernel(const int* __restrict__ esrc, const int* __restrict__ edst) {
    int e = blockIdx.x * blockDim.x + threadIdx.x;
    if (e < NEDGE) { atomicAdd(&g_deg_out[esrc[e]], 1); atomicAdd(&g_deg_in[edst[e]], 1); }
}
__global__ void dinv_kernel() {
    int i = blockIdx.x * blockDim.x + threadIdx.x;
    if (i < NNODES) {
        int dout = g_deg_out[i]; if (dout < 1) dout = 1;
        int din  = g_deg_in[i];  if (din  < 1) din  = 1;
        g_dinv_out[i] = rsqrtf((float)dout);
        g_dinv_in[i]  = rsqrtf((float)din);
    }
}
__global__ void scan_kernel() {
    __shared__ int warp_sums[32];
    __shared__ int s_carry;
    int t = threadIdx.x, lane = t & 31, wid = t >> 5;
    if (t == 0) { s_carry = 0; g_offs[0] = 0; }
    __syncthreads();
    for (int base = 0; base < NNODES; base += 1024) {
        int idx = base + t;
        int x = (idx < NNODES) ? g_deg_in[idx] : 0;
#pragma unroll
        for (int o = 1; o < 32; o <<= 1) {
            int y = __shfl_up_sync(0xFFFFFFFFu, x, o);
            if (lane >= o) x += y;
        }
        if (lane == 31) warp_sums[wid] = x;
        __syncthreads();
        if (wid == 0) {
            int ws = warp_sums[lane];
#pragma unroll
            for (int o = 1; o < 32; o <<= 1) {
                int y = __shfl_up_sync(0xFFFFFFFFu, ws, o);
                if (lane >= o) ws += y;
            }
            warp_sums[lane] = ws;
        }
        __syncthreads();
        int incl = x + s_carry + (wid > 0 ? warp_sums[wid - 1] : 0);
        if (idx < NNODES) g_offs[idx + 1] = incl;
        __syncthreads();
        if (t == 1023) s_carry = incl;
        __syncthreads();
    }
}
__global__ void fill_csr_kernel(const int* __restrict__ esrc, const int* __restrict__ edst) {
    int e = blockIdx.x * blockDim.x + threadIdx.x;
    if (e < NEDGE) {
        int s = esrc[e], d = edst[e];
        int pos = g_offs[d] + atomicAdd(&g_cursor[d], 1);
        g_col[pos] = s;
        g_w[pos] = g_dinv_out[s] * g_dinv_in[d];
    }
}

// ---------------- weight transpose + bf16 hi/lo split ----------------
__global__ void transpose_split_kernel(const float* __restrict__ in,
                                       __nv_bfloat16* __restrict__ oh,
                                       __nv_bfloat16* __restrict__ ol, int R, int C) {
    __shared__ float tile[32][33];
    int c0 = blockIdx.x * 32, r0 = blockIdx.y * 32;
    int x = threadIdx.x, y = threadIdx.y;   // 32 x 8
#pragma unroll
    for (int j = 0; j < 32; j += 8)
        tile[y + j][x] = in[(size_t)(r0 + y + j) * C + c0 + x];
    __syncthreads();
#pragma unroll
    for (int j = 0; j < 32; j += 8) {
        float v = tile[x][y + j];
        size_t o = (size_t)(c0 + y + j) * R + r0 + x;
        __nv_bfloat16 h = __float2bfloat16(v);
        oh[o] = h;
        ol[o] = __float2bfloat16(v - __bfloat162float(h));
    }
}

// ---------------- build node features + layernorm -> g_x ----------------
__global__ void build_ln_kernel(const float* __restrict__ mhs,
                                const float* __restrict__ ehs,
                                const float* __restrict__ shs,
                                const float* __restrict__ temb,
                                const float* __restrict__ scale,
                                const float* __restrict__ bias) {
    int node = blockIdx.x;
    int b = node / NPB;
    int i = node - b * NPB;
    int t = threadIdx.x;
    int c = t * 4;

    const float* src;
    int type;
    if (i < NM)           { type = 0; src = mhs + ((size_t)b * NM + i) * HDIM; }
    else if (i < NM + NE) { type = 1; src = ehs + ((size_t)b * NE + (i - NM)) * HDIM; }
    else                  { type = 2; src = shs + ((size_t)b * NS + (i - NM - NE)) * HDIM; }

    float4 v;
    if (c < HDIM) v = *(const float4*)(src + c);
    else          v = *(const float4*)(temb + type * TDIM + (c - HDIM));

    float s1 = v.x + v.y + v.z + v.w;
    float s2 = v.x * v.x + v.y * v.y + v.z * v.z + v.w * v.w;

    __shared__ float sh1[8], sh2[8], s_mu, s_r;
    int lane = t & 31, wid = t >> 5;
#pragma unroll
    for (int o = 16; o > 0; o >>= 1) {
        s1 += __shfl_down_sync(0xFFFFFFFFu, s1, o);
        s2 += __shfl_down_sync(0xFFFFFFFFu, s2, o);
    }
    if (lane == 0) { sh1[wid] = s1; sh2[wid] = s2; }
    __syncthreads();
    if (wid == 0) {
        s1 = (lane < 8) ? sh1[lane] : 0.f;
        s2 = (lane < 8) ? sh2[lane] : 0.f;
#pragma unroll
        for (int o = 4; o > 0; o >>= 1) {
            s1 += __shfl_down_sync(0xFFFFFFFFu, s1, o);
            s2 += __shfl_down_sync(0xFFFFFFFFu, s2, o);
        }
        if (lane == 0) {
            float mu = s1 / (float)DDIM;
            float var = s2 / (float)DDIM - mu * mu;
            s_mu = mu; s_r = rsqrtf(var + LN_EPS);
        }
    }
    __syncthreads();
    float mu = s_mu, r = s_r;
    float4 sc = *(const float4*)(scale + c);
    float4 bi = *(const float4*)(bias + c);
    float4 o;
    o.x = (v.x - mu) * r * sc.x + bi.x;
    o.y = (v.y - mu) * r * sc.y + bi.y;
    o.z = (v.z - mu) * r * sc.z + bi.z;
    o.w = (v.w - mu) * r * sc.w + bi.w;
    *(float4*)(g_x + (size_t)node * DDIM + c) = o;
}

// ---------------- aggregation: fp32 accumulate, bf16 hi/lo output ----------------
__global__ void aggregate_kernel() {
    int node = blockIdx.x;
    int t = threadIdx.x;
    int beg = g_offs[node], end = g_offs[node + 1];

    __shared__ int   s_col[256];
    __shared__ float s_w[256];
    const float4* x4 = (const float4*)g_x;

    float4 acc = make_float4(0.f, 0.f, 0.f, 0.f);
    for (int base = beg; base < end; base += 256) {
        int n = end - base; if (n > 256) n = 256;
        if (t < n) { s_col[t] = g_col[base + t]; s_w[t] = g_w[base + t]; }
        __syncthreads();
        for (int i = 0; i < n; i++) {
            float  ww = s_w[i];
            float4 v  = x4[(size_t)s_col[i] * 256 + t];
            acc.x += ww * v.x; acc.y += ww * v.y;
            acc.z += ww * v.z; acc.w += ww * v.w;
        }
        __syncthreads();
    }
    split4_store(acc, g_a_hi, g_a_lo, (size_t)node * DDIM + t * 4);
}

// ---------------- gather entity rows of g_x -> packed hi/lo ----------------
__global__ void split_entity_kernel() {
    int row = blockIdx.x;
    int b = row / NE, e = row - b * NE;
    int t = threadIdx.x;
    float4 v = *(const float4*)(g_x + ((size_t)(b * NPB + NM + e)) * DDIM + t * 4);
    split4_store(v, g_a_hi, g_a_lo, (size_t)row * DDIM + t * 4);
}

// ---------------- HMMA bf16x3 GEMM ----------------
// C[M x Nout] = act( (Ahi+Alo) @ (Bhi+Blo)^T + bias ), K = 1024 fixed.
// CTA 128x128, BK=32, 256 thr / 8 warps (2x4), warp tile 64x32, m16n8k16.
#define BM 128
#define BN 128
#define BK 32
#define SKB 40                      // smem row stride (bf16 elems), conflict-free
#define TILE_E (BM * SKB)           // elems per tile
#define NSTAGE 2
#define GEMM_SMEM (NSTAGE * 4 * TILE_E * 2)   // 81920 bytes

__global__ void __launch_bounds__(256)
mma_gemm_kernel(const __nv_bfloat16* __restrict__ Ahi, const __nv_bfloat16* __restrict__ Alo,
                const __nv_bfloat16* __restrict__ Bhi, const __nv_bfloat16* __restrict__ Blo,
                const float* __restrict__ bias, float* __restrict__ Cout,
                int Nout, int relu) {
    extern __shared__ __nv_bfloat16 sm[];
    uint32_t sbase = smem_u32(sm);

    const int t = threadIdx.x, lane = t & 31, wid = t >> 5;
    const int wm = wid & 1, wn = wid >> 1;          // warp grid 2(M) x 4(N)
    const int row0 = blockIdx.y * BM, col0 = blockIdx.x * BN;

    // gmem->smem staging: thread t loads 2 consecutive uint4 per tile
    const int r = t >> 1, cpair = (t & 1) * 2;      // r: 0..127, cpair: 0 or 2
    const uint4* gAh = (const uint4*)Ahi + (size_t)(row0 + r) * 128;
    const uint4* gAl = (const uint4*)Alo + (size_t)(row0 + r) * 128;
    const uint4* gBh = (const uint4*)Bhi + (size_t)(col0 + r) * 128;
    const uint4* gBl = (const uint4*)Blo + (size_t)(col0 + r) * 128;

    uint4 rAh[2], rAl[2], rBh[2], rBl[2];
    const int sidx0 = r * SKB + cpair * 8;          // elem index of first uint4
    const int sidx1 = sidx0 + 8;

    float acc[4][4][4];
#pragma unroll
    for (int mt = 0; mt < 4; mt++)
#pragma unroll
        for (int nt = 0; nt < 4; nt++)
#pragma unroll
            for (int k = 0; k < 4; k++) acc[mt][nt][k] = 0.f;

    const int nk = 1024 / BK;                        // 32

    // prologue
    {
        int off = cpair;
        rAh[0] = gAh[off]; rAh[1] = gAh[off + 1];
        rAl[0] = gAl[off]; rAl[1] = gAl[off + 1];
        rBh[0] = gBh[off]; rBh[1] = gBh[off + 1];
        rBl[0] = gBl[off]; rBl[1] = gBl[off + 1];
        __nv_bfloat16* s0 = sm;                      // stage 0
        *(uint4*)(s0 + 0 * TILE_E + sidx0) = rAh[0]; *(uint4*)(s0 + 0 * TILE_E + sidx1) = rAh[1];
        *(uint4*)(s0 + 1 * TILE_E + sidx0) = rAl[0]; *(uint4*)(s0 + 1 * TILE_E + sidx1) = rAl[1];
        *(uint4*)(s0 + 2 * TILE_E + sidx0) = rBh[0]; *(uint4*)(s0 + 2 * TILE_E + sidx1) = rBh[1];
        *(uint4*)(s0 + 3 * TILE_E + sidx0) = rBl[0]; *(uint4*)(s0 + 3 * TILE_E + sidx1) = rBl[1];
    }
    __syncthreads();

    // ldmatrix per-lane address components
    const int asel = lane >> 3;
    const int arowoff = (asel & 1) * 8 + (lane & 7);
    const int akadd = (asel >> 1) * 8;
    const int browoff = lane & 7;
    const int bkadd = ((lane >> 3) & 1) * 8;

    for (int k0 = 0; k0 < nk; k0++) {
        if (k0 + 1 < nk) {
            int off = (k0 + 1) * 4 + cpair;
            rAh[0] = gAh[off]; rAh[1] = gAh[off + 1];
            rAl[0] = gAl[off]; rAl[1] = gAl[off + 1];
            rBh[0] = gBh[off]; rBh[1] = gBh[off + 1];
            rBl[0] = gBl[off]; rBl[1] = gBl[off + 1];
        }

        // compute on stage k0&1
        {
            uint32_t base = sbase + (uint32_t)((k0 & 1) * 4 * TILE_E * 2);
            uint32_t bAh = base;
            uint32_t bAl = base + TILE_E * 2;
            uint32_t bBh = base + 2 * TILE_E * 2;
            uint32_t bBl = base + 3 * TILE_E * 2;
#pragma unroll
            for (int ks = 0; ks < 2; ks++) {
                const int kk = ks * 16;
                uint32_t ah[4][4], al[4][4], bh[4][2], bl[4][2];
#pragma unroll
                for (int mt = 0; mt < 4; mt++) {
                    int rrow = wm * 64 + mt * 16 + arowoff;
                    uint32_t ao = (uint32_t)((rrow * SKB + kk + akadd) * 2);
                    LDSM4(ah[mt], bAh + ao);
                    LDSM4(al[mt], bAl + ao);
                }
#pragma unroll
                for (int nt = 0; nt < 4; nt++) {
                    int nrow = wn * 32 + nt * 8 + browoff;
                    uint32_t bo = (uint32_t)((nrow * SKB + kk + bkadd) * 2);
                    LDSM2(bh[nt], bBh + bo);
                    LDSM2(bl[nt], bBl + bo);
                }
                // product-major to break accumulator RAW chains
#pragma unroll
                for (int mt = 0; mt < 4; mt++)
#pragma unroll
                    for (int nt = 0; nt < 4; nt++) MMA16816(acc[mt][nt], ah[mt], bh[nt]);
#pragma unroll
                for (int mt = 0; mt < 4; mt++)
#pragma unroll
                    for (int nt = 0; nt < 4; nt++) MMA16816(acc[mt][nt], ah[mt], bl[nt]);
#pragma unroll
                for (int mt = 0; mt < 4; mt++)
#pragma unroll
                    for (int nt = 0; nt < 4; nt++) MMA16816(acc[mt][nt], al[mt], bh[nt]);
            }
        }

        if (k0 + 1 < nk) {
            __nv_bfloat16* s1 = sm + ((k0 + 1) & 1) * 4 * TILE_E;
            *(uint4*)(s1 + 0 * TILE_E + sidx0) = rAh[0]; *(uint4*)(s1 + 0 * TILE_E + sidx1) = rAh[1];
            *(uint4*)(s1 + 1 * TILE_E + sidx0) = rAl[0]; *(uint4*)(s1 + 1 * TILE_E + sidx1) = rAl[1];
            *(uint4*)(s1 + 2 * TILE_E + sidx0) = rBh[0]; *(uint4*)(s1 + 2 * TILE_E + sidx1) = rBh[1];
            *(uint4*)(s1 + 3 * TILE_E + sidx0) = rBl[0]; *(uint4*)(s1 + 3 * TILE_E + sidx1) = rBl[1];
        }
        __syncthreads();
    }

    // epilogue
    const int rbase = row0 + wm * 64 + (lane >> 2);
    const int cbase = col0 + wn * 32 + (lane & 3) * 2;
#pragma unroll
    for (int nt = 0; nt < 4; nt++) {
        int col = cbase + nt * 8;
        float b0 = bias[col], b1 = bias[col + 1];
#pragma unroll
        for (int mt = 0; mt < 4; mt++) {
            int rrow = rbase + mt * 16;
            float v0 = acc[mt][nt][0] + b0;
            float v1 = acc[mt][nt][1] + b1;
            float v2 = acc[mt][nt][2] + b0;
            float v3 = acc[mt][nt][3] + b1;
            if (relu) {
                v0 = (v0 > 0.f) ? v0 : LRELU * v0;
                v1 = (v1 > 0.f) ? v1 : LRELU * v1;
                v2 = (v2 > 0.f) ? v2 : LRELU * v2;
                v3 = (v3 > 0.f) ? v3 : LRELU * v3;
            }
            *(float2*)(Cout + (size_t)rrow * Nout + col) = make_float2(v0, v1);
            *(float2*)(Cout + (size_t)(rrow + 8) * Nout + col) = make_float2(v2, v3);
        }
    }
}

// ---------------- launch ----------------
extern "C" void kernel_launch(void* const* d_in, const int* in_sizes, int n_in,
                              void* d_out, int out_size) {
    const float* mhs  = (const float*)d_in[0];
    const float* ehs  = (const float*)d_in[1];
    const float* shs  = (const float*)d_in[2];
    const int*   esrc = (const int*)d_in[3];
    const int*   edst = (const int*)d_in[4];
    const float* temb = (const float*)d_in[5];
    const float* lns  = (const float*)d_in[6];
    const float* lnb  = (const float*)d_in[7];
    const float* gw   = (const float*)d_in[8];
    const float* gb   = (const float*)d_in[9];
    const float* fcw  = (const float*)d_in[10];
    const float* fcb  = (const float*)d_in[11];
    float* out = (float*)d_out;

    cudaFuncSetAttribute(mma_gemm_kernel, cudaFuncAttributeMaxDynamicSharedMemorySize, GEMM_SMEM);

    __nv_bfloat16 *wt_hi, *wt_lo, *fcw_hi, *fcw_lo, *a_hi, *a_lo;
    cudaGetSymbolAddress((void**)&wt_hi,  g_wt_hi);
    cudaGetSymbolAddress((void**)&wt_lo,  g_wt_lo);
    cudaGetSymbolAddress((void**)&fcw_hi, g_fcw_hi);
    cudaGetSymbolAddress((void**)&fcw_lo, g_fcw_lo);
    cudaGetSymbolAddress((void**)&a_hi,   g_a_hi);
    cudaGetSymbolAddress((void**)&a_lo,   g_a_lo);
    float* xptr; cudaGetSymbolAddress((void**)&xptr, g_x);

    // graph preprocessing (reused by all 3 layers)
    zero_counters_kernel<<<(NNODES + 255) / 256, 256>>>();
    degree_kernel<<<(NEDGE + 255) / 256, 256>>>(esrc, edst);
    dinv_kernel<<<(NNODES + 255) / 256, 256>>>();
    scan_kernel<<<1, 1024>>>();
    fill_csr_kernel<<<(NEDGE + 255) / 256, 256>>>(esrc, edst);

    // weights: transpose to [N][K] + bf16 hi/lo split
    for (int l = 0; l < NLAYER; l++)
        transpose_split_kernel<<<dim3(DDIM / 32, DDIM / 32), dim3(32, 8)>>>(
            gw + (size_t)l * DDIM * DDIM,
            wt_hi + (size_t)l * DDIM * DDIM,
            wt_lo + (size_t)l * DDIM * DDIM, DDIM, DDIM);
    transpose_split_kernel<<<dim3(OUTF / 32, DDIM / 32), dim3(32, 8)>>>(
        fcw, fcw_hi, fcw_lo, DDIM, OUTF);

    // features + layernorm -> g_x
    build_ln_kernel<<<NNODES, 256>>>(mhs, ehs, shs, temb, lns, lnb);

    // 3 GCN layers
    for (int l = 0; l < NLAYER; l++) {
        aggregate_kernel<<<NNODES, 256>>>();
        mma_gemm_kernel<<<dim3(DDIM / 128, NNODES / 128), 256, GEMM_SMEM>>>(
            a_hi, a_lo,
            wt_hi + (size_t)l * DDIM * DDIM, wt_lo + (size_t)l * DDIM * DDIM,
            gb + (size_t)l * DDIM, xptr, DDIM, /*relu=*/1);
    }

    // final fc on entity rows only
    split_entity_kernel<<<NENT, 256>>>();
    mma_gemm_kernel<<<dim3(OUTF / 128, NENT / 128), 256, GEMM_SMEM>>>(
        a_hi, a_lo, fcw_hi, fcw_lo, fcb, out, OUTF, /*relu=*/0);
}

// round 4
// speedup vs baseline: 2.5434x; 1.2908x over previous
#include <cuda_runtime.h>
#include <cuda_fp16.h>
#include <cstdint>

// ---------------- problem constants ----------------
#define NBATCH   128
#define NM       100
#define NE       50
#define NS       25
#define NPB      175
#define NNODES   (NBATCH*NPB)   // 22400
#define HDIM     768
#define TDIM     256
#define DDIM     1024
#define OUTF     768
#define NLAYER   3
#define NEDGE    716800
#define NENT     (NBATCH*NE)    // 6400
#define LRELU    0.01f
#define LN_EPS   1e-5f

// ---------------- device scratch ----------------
__device__ __align__(16) float   g_x[(size_t)NNODES * DDIM];
__device__ __align__(16) __half  g_a_hi[(size_t)NNODES * DDIM];
__device__ __align__(16) __half  g_a_lo[(size_t)NNODES * DDIM];
__device__ __align__(16) __half  g_wt[(size_t)NLAYER * DDIM * DDIM];
__device__ __align__(16) __half  g_fcw[(size_t)OUTF * DDIM];
__device__ int   g_deg_out[NNODES];
__device__ int   g_deg_in[NNODES];
__device__ float g_dinv_out[NNODES];
__device__ float g_dinv_in[NNODES];
__device__ int   g_offs[NNODES + 1];
__device__ int   g_cursor[NNODES];
__device__ int   g_col[NEDGE];
__device__ float g_w[NEDGE];

// ---------------- helpers ----------------
__device__ __forceinline__ uint32_t smem_u32(const void* p) {
    uint32_t a;
    asm("{ .reg .u64 t; cvta.to.shared.u64 t, %1; cvt.u32.u64 %0, t; }" : "=r"(a) : "l"(p));
    return a;
}
#define LDSM4(r, addr) \
    asm volatile("ldmatrix.sync.aligned.m8n8.x4.shared.b16 {%0,%1,%2,%3}, [%4];" \
        : "=r"((r)[0]), "=r"((r)[1]), "=r"((r)[2]), "=r"((r)[3]) : "r"(addr))
#define LDSM2(r, addr) \
    asm volatile("ldmatrix.sync.aligned.m8n8.x2.shared.b16 {%0,%1}, [%2];" \
        : "=r"((r)[0]), "=r"((r)[1]) : "r"(addr))
#define MMA16816(d, a, b) \
    asm volatile("mma.sync.aligned.m16n8k16.row.col.f32.f16.f16.f32 " \
        "{%0,%1,%2,%3}, {%4,%5,%6,%7}, {%8,%9}, {%0,%1,%2,%3};" \
        : "+f"((d)[0]), "+f"((d)[1]), "+f"((d)[2]), "+f"((d)[3]) \
        : "r"((a)[0]), "r"((a)[1]), "r"((a)[2]), "r"((a)[3]), "r"((b)[0]), "r"((b)[1]))
#define CP16(dst, src) \
    asm volatile("cp.async.cg.shared.global [%0], [%1], 16;" :: "r"(dst), "l"(src) : "memory")
#define CP_COMMIT() asm volatile("cp.async.commit_group;" ::: "memory")
#define CP_WAIT1()  asm volatile("cp.async.wait_group 1;" ::: "memory")

__device__ __forceinline__ void split4h(float4 v, __half* hi, __half* lo, size_t eidx) {
    __half h[4], l[4];
    float f[4] = {v.x, v.y, v.z, v.w};
#pragma unroll
    for (int k = 0; k < 4; k++) {
        h[k] = __float2half_rn(f[k]);
        l[k] = __float2half_rn(f[k] - __half2float(h[k]));
    }
    *(uint2*)(hi + eidx) = *(uint2*)h;
    *(uint2*)(lo + eidx) = *(uint2*)l;
}

// ---------------- fused prep: build_ln + zero counters + weight transposes ----------------
// blockIdx ranges: [0, NNODES) -> build_ln ; [NNODES, NNODES+88) -> zero ;
// rest -> transpose-to-fp16 of 3 layer weights (32x32 grid each) + fc (24x32)
#define ZBLKS 88
#define TBLKS (3 * 1024 + 24 * 32)   // 3840

__global__ void __launch_bounds__(256)
fused_prep_kernel(const float* __restrict__ mhs, const float* __restrict__ ehs,
                  const float* __restrict__ shs, const float* __restrict__ temb,
                  const float* __restrict__ scale, const float* __restrict__ bias,
                  const float* __restrict__ gw, const float* __restrict__ fcw) {
    __shared__ float tile[32][33];
    __shared__ float sh1[8], sh2[8], s_mu, s_r;
    int bx = blockIdx.x;
    int t = threadIdx.x;

    if (bx < NNODES) {
        // ---- build node features + layernorm ----
        int node = bx;
        int b = node / NPB;
        int i = node - b * NPB;
        int c = t * 4;

        const float* src;
        int type;
        if (i < NM)           { type = 0; src = mhs + ((size_t)b * NM + i) * HDIM; }
        else if (i < NM + NE) { type = 1; src = ehs + ((size_t)b * NE + (i - NM)) * HDIM; }
        else                  { type = 2; src = shs + ((size_t)b * NS + (i - NM - NE)) * HDIM; }

        float4 v;
        if (c < HDIM) v = *(const float4*)(src + c);
        else          v = *(const float4*)(temb + type * TDIM + (c - HDIM));

        float s1 = v.x + v.y + v.z + v.w;
        float s2 = v.x * v.x + v.y * v.y + v.z * v.z + v.w * v.w;
        int lane = t & 31, wid = t >> 5;
#pragma unroll
        for (int o = 16; o > 0; o >>= 1) {
            s1 += __shfl_down_sync(0xFFFFFFFFu, s1, o);
            s2 += __shfl_down_sync(0xFFFFFFFFu, s2, o);
        }
        if (lane == 0) { sh1[wid] = s1; sh2[wid] = s2; }
        __syncthreads();
        if (wid == 0) {
            s1 = (lane < 8) ? sh1[lane] : 0.f;
            s2 = (lane < 8) ? sh2[lane] : 0.f;
#pragma unroll
            for (int o = 4; o > 0; o >>= 1) {
                s1 += __shfl_down_sync(0xFFFFFFFFu, s1, o);
                s2 += __shfl_down_sync(0xFFFFFFFFu, s2, o);
            }
            if (lane == 0) {
                float mu = s1 / (float)DDIM;
                float var = s2 / (float)DDIM - mu * mu;
                s_mu = mu; s_r = rsqrtf(var + LN_EPS);
            }
        }
        __syncthreads();
        float mu = s_mu, r = s_r;
        float4 sc = *(const float4*)(scale + c);
        float4 bi = *(const float4*)(bias + c);
        float4 o;
        o.x = (v.x - mu) * r * sc.x + bi.x;
        o.y = (v.y - mu) * r * sc.y + bi.y;
        o.z = (v.z - mu) * r * sc.z + bi.z;
        o.w = (v.w - mu) * r * sc.w + bi.w;
        *(float4*)(g_x + (size_t)node * DDIM + c) = o;
    } else if (bx < NNODES + ZBLKS) {
        int i = (bx - NNODES) * 256 + t;
        if (i < NNODES) { g_deg_out[i] = 0; g_deg_in[i] = 0; g_cursor[i] = 0; }
    } else {
        // ---- transpose + fp16 convert: in [R][C] fp32 -> out [C][R] fp16 ----
        int ti = bx - NNODES - ZBLKS;
        const float* in; __half* oh; int R, C, bxx, byy;
        if (ti < 3072) {
            int l = ti >> 10, rr = ti & 1023;
            bxx = rr & 31; byy = rr >> 5;
            in = gw + (size_t)l * DDIM * DDIM;
            oh = g_wt + (size_t)l * DDIM * DDIM;
            R = DDIM; C = DDIM;
        } else {
            int rr = ti - 3072;
            bxx = rr % 24; byy = rr / 24;
            in = fcw; oh = g_fcw; R = DDIM; C = OUTF;
        }
        int c0 = bxx * 32, r0 = byy * 32;
        int x = t & 31, y = t >> 5;   // 32 x 8
#pragma unroll
        for (int j = 0; j < 32; j += 8)
            tile[y + j][x] = in[(size_t)(r0 + y + j) * C + c0 + x];
        __syncthreads();
#pragma unroll
        for (int j = 0; j < 32; j += 8) {
            float v = tile[x][y + j];
            oh[(size_t)(c0 + y + j) * R + r0 + x] = __float2half_rn(v);
        }
    }
}

// ---------------- graph preprocessing ----------------
__global__ void degree_kernel(const int* __restrict__ esrc, const int* __restrict__ edst) {
    int e = blockIdx.x * blockDim.x + threadIdx.x;
    if (e < NEDGE) { atomicAdd(&g_deg_out[esrc[e]], 1); atomicAdd(&g_deg_in[edst[e]], 1); }
}
// scan of g_deg_in -> g_offs, plus dinv computation folded in
__global__ void scan_dinv_kernel() {
    __shared__ int warp_sums[32];
    __shared__ int s_carry;
    int t = threadIdx.x, lane = t & 31, wid = t >> 5;
    if (t == 0) { s_carry = 0; g_offs[0] = 0; }
    __syncthreads();
    for (int base = 0; base < NNODES; base += 1024) {
        int idx = base + t;
        int din = (idx < NNODES) ? g_deg_in[idx] : 0;
        if (idx < NNODES) {
            int dout = g_deg_out[idx]; if (dout < 1) dout = 1;
            int dc = din; if (dc < 1) dc = 1;
            g_dinv_out[idx] = rsqrtf((float)dout);
            g_dinv_in[idx]  = rsqrtf((float)dc);
        }
        int x = din;
#pragma unroll
        for (int o = 1; o < 32; o <<= 1) {
            int y = __shfl_up_sync(0xFFFFFFFFu, x, o);
            if (lane >= o) x += y;
        }
        if (lane == 31) warp_sums[wid] = x;
        __syncthreads();
        if (wid == 0) {
            int ws = warp_sums[lane];
#pragma unroll
            for (int o = 1; o < 32; o <<= 1) {
                int y = __shfl_up_sync(0xFFFFFFFFu, ws, o);
                if (lane >= o) ws += y;
            }
            warp_sums[lane] = ws;
        }
        __syncthreads();
        int incl = x + s_carry + (wid > 0 ? warp_sums[wid - 1] : 0);
        if (idx < NNODES) g_offs[idx + 1] = incl;
        __syncthreads();
        if (t == 1023) s_carry = incl;
        __syncthreads();
    }
}
__global__ void fill_csr_kernel(const int* __restrict__ esrc, const int* __restrict__ edst) {
    int e = blockIdx.x * blockDim.x + threadIdx.x;
    if (e < NEDGE) {
        int s = esrc[e], d = edst[e];
        int pos = g_offs[d] + atomicAdd(&g_cursor[d], 1);
        g_col[pos] = s;
        g_w[pos] = g_dinv_out[s] * g_dinv_in[d];
    }
}

// ---------------- aggregation: fp32 accumulate, fp16 hi/lo output ----------------
__global__ void aggregate_kernel() {
    int node = blockIdx.x;
    int t = threadIdx.x;
    int beg = g_offs[node], end = g_offs[node + 1];

    __shared__ int   s_col[256];
    __shared__ float s_w[256];
    const float4* x4 = (const float4*)g_x;

    float4 acc = make_float4(0.f, 0.f, 0.f, 0.f);
    for (int base = beg; base < end; base += 256) {
        int n = end - base; if (n > 256) n = 256;
        if (t < n) { s_col[t] = g_col[base + t]; s_w[t] = g_w[base + t]; }
        __syncthreads();
#pragma unroll 2
        for (int i = 0; i < n; i++) {
            float  ww = s_w[i];
            float4 v  = x4[(size_t)s_col[i] * 256 + t];
            acc.x += ww * v.x; acc.y += ww * v.y;
            acc.z += ww * v.z; acc.w += ww * v.w;
        }
        __syncthreads();
    }
    split4h(acc, g_a_hi, g_a_lo, (size_t)node * DDIM + t * 4);
}

// ---------------- gather entity rows of g_x -> packed fp16 hi/lo ----------------
__global__ void split_entity_kernel() {
    int row = blockIdx.x;
    int b = row / NE, e = row - b * NE;
    int t = threadIdx.x;
    float4 v = *(const float4*)(g_x + ((size_t)(b * NPB + NM + e)) * DDIM + t * 4);
    split4h(v, g_a_hi, g_a_lo, (size_t)row * DDIM + t * 4);
}

// ---------------- HMMA fp16x2 GEMM ----------------
// C[M x Nout] = act( (Ahi+Alo) @ B^T + bias ), K = 1024, B single fp16.
// CTA 128x128, BK=32, 256 thr / 8 warps (2x4), warp tile 64x32, m16n8k16.
// 3-stage cp.async pipeline, 3 smem tiles (Ah, Al, B) per stage.
#define BM 128
#define BN 128
#define BK 32
#define SKB 40
#define TILE_E (BM * SKB)                 // 5120 halfs = 10240 B
#define NST 3
#define GEMM_SMEM (NST * 3 * TILE_E * 2)  // 92160 B

__global__ void __launch_bounds__(256)
mma_gemm_kernel(const __half* __restrict__ Ahi, const __half* __restrict__ Alo,
                const __half* __restrict__ B, const float* __restrict__ bias,
                float* __restrict__ Cout, int Nout, int relu) {
    extern __shared__ __half sm[];
    uint32_t sbase = smem_u32(sm);

    const int t = threadIdx.x, lane = t & 31, wid = t >> 5;
    const int wm = wid & 1, wn = wid >> 1;
    const int row0 = blockIdx.y * BM, col0 = blockIdx.x * BN;

    const int r = t >> 1, cpair = (t & 1) * 2;
    const uint4* gAh = (const uint4*)Ahi + (size_t)(row0 + r) * 128;   // row pitch: 1024 halfs = 128 uint4
    const uint4* gAl = (const uint4*)Alo + (size_t)(row0 + r) * 128;
    const uint4* gB  = (const uint4*)B   + (size_t)(col0 + r) * 128;
    const uint32_t so0 = (uint32_t)(r * SKB + cpair * 8) * 2;          // bytes
    const uint32_t so1 = so0 + 16;

    float acc[4][4][4];
#pragma unroll
    for (int mt = 0; mt < 4; mt++)
#pragma unroll
        for (int nt = 0; nt < 4; nt++)
#pragma unroll
            for (int k = 0; k < 4; k++) acc[mt][nt][k] = 0.f;

    const int nk = 1024 / BK;   // 32

#define ISSUE(k0, st) do { \
        int off = (k0) * 4 + cpair; \
        uint32_t sb_ = sbase + (uint32_t)((st) * 3 * TILE_E * 2); \
        CP16(sb_ + so0, gAh + off); CP16(sb_ + so1, gAh + off + 1); \
        CP16(sb_ + TILE_E * 2 + so0, gAl + off); CP16(sb_ + TILE_E * 2 + so1, gAl + off + 1); \
        CP16(sb_ + 2 * TILE_E * 2 + so0, gB + off); CP16(sb_ + 2 * TILE_E * 2 + so1, gB + off + 1); \
    } while (0)

    ISSUE(0, 0); CP_COMMIT();
    ISSUE(1, 1); CP_COMMIT();

    const int asel = lane >> 3;
    const int arowoff = (asel & 1) * 8 + (lane & 7);
    const int akadd = (asel >> 1) * 8;
    const int browoff = lane & 7;
    const int bkadd = ((lane >> 3) & 1) * 8;

    for (int k0 = 0; k0 < nk; k0++) {
        CP_WAIT1();
        __syncthreads();
        if (k0 + 2 < nk) ISSUE(k0 + 2, (k0 + 2) % 3);
        CP_COMMIT();

        uint32_t base = sbase + (uint32_t)((k0 % 3) * 3 * TILE_E * 2);
        uint32_t bAh = base;
        uint32_t bAl = base + TILE_E * 2;
        uint32_t bB  = base + 2 * TILE_E * 2;
#pragma unroll
        for (int ks = 0; ks < 2; ks++) {
            const int kk = ks * 16;
            uint32_t ah[4][4], al[4][4], bb[4][2];
#pragma unroll
            for (int mt = 0; mt < 4; mt++) {
                int rrow = wm * 64 + mt * 16 + arowoff;
                uint32_t ao = (uint32_t)((rrow * SKB + kk + akadd) * 2);
                LDSM4(ah[mt], bAh + ao);
                LDSM4(al[mt], bAl + ao);
            }
#pragma unroll
            for (int nt = 0; nt < 4; nt++) {
                int nrow = wn * 32 + nt * 8 + browoff;
                uint32_t bo = (uint32_t)((nrow * SKB + kk + bkadd) * 2);
                LDSM2(bb[nt], bB + bo);
            }
#pragma unroll
            for (int mt = 0; mt < 4; mt++)
#pragma unroll
                for (int nt = 0; nt < 4; nt++) MMA16816(acc[mt][nt], ah[mt], bb[nt]);
#pragma unroll
            for (int mt = 0; mt < 4; mt++)
#pragma unroll
                for (int nt = 0; nt < 4; nt++) MMA16816(acc[mt][nt], al[mt], bb[nt]);
        }
        __syncthreads();
    }
#undef ISSUE

    // epilogue
    const int rbase = row0 + wm * 64 + (lane >> 2);
    const int cbase = col0 + wn * 32 + (lane & 3) * 2;
#pragma unroll
    for (int nt = 0; nt < 4; nt++) {
        int col = cbase + nt * 8;
        float b0 = bias[col], b1 = bias[col + 1];
#pragma unroll
        for (int mt = 0; mt < 4; mt++) {
            int rrow = rbase + mt * 16;
            float v0 = acc[mt][nt][0] + b0;
            float v1 = acc[mt][nt][1] + b1;
            float v2 = acc[mt][nt][2] + b0;
            float v3 = acc[mt][nt][3] + b1;
            if (relu) {
                v0 = (v0 > 0.f) ? v0 : LRELU * v0;
                v1 = (v1 > 0.f) ? v1 : LRELU * v1;
                v2 = (v2 > 0.f) ? v2 : LRELU * v2;
                v3 = (v3 > 0.f) ? v3 : LRELU * v3;
            }
            *(float2*)(Cout + (size_t)rrow * Nout + col) = make_float2(v0, v1);
            *(float2*)(Cout + (size_t)(rrow + 8) * Nout + col) = make_float2(v2, v3);
        }
    }
}

// ---------------- launch ----------------
extern "C" void kernel_launch(void* const* d_in, const int* in_sizes, int n_in,
                              void* d_out, int out_size) {
    const float* mhs  = (const float*)d_in[0];
    const float* ehs  = (const float*)d_in[1];
    const float* shs  = (const float*)d_in[2];
    const int*   esrc = (const int*)d_in[3];
    const int*   edst = (const int*)d_in[4];
    const float* temb = (const float*)d_in[5];
    const float* lns  = (const float*)d_in[6];
    const float* lnb  = (const float*)d_in[7];
    const float* gw   = (const float*)d_in[8];
    const float* gb   = (const float*)d_in[9];
    const float* fcw  = (const float*)d_in[10];
    const float* fcb  = (const float*)d_in[11];
    float* out = (float*)d_out;

    cudaFuncSetAttribute(mma_gemm_kernel, cudaFuncAttributeMaxDynamicSharedMemorySize, GEMM_SMEM);

    __half *wt, *fcw_h, *a_hi, *a_lo;
    cudaGetSymbolAddress((void**)&wt,    g_wt);
    cudaGetSymbolAddress((void**)&fcw_h, g_fcw);
    cudaGetSymbolAddress((void**)&a_hi,  g_a_hi);
    cudaGetSymbolAddress((void**)&a_lo,  g_a_lo);
    float* xptr; cudaGetSymbolAddress((void**)&xptr, g_x);

    // launch 0: fused prep (LN features + counter zero + weight transposes)
    fused_prep_kernel<<<NNODES + ZBLKS + TBLKS, 256>>>(mhs, ehs, shs, temb, lns, lnb, gw, fcw);
    // launches 1-3: graph preprocessing
    degree_kernel<<<(NEDGE + 255) / 256, 256>>>(esrc, edst);
    scan_dinv_kernel<<<1, 1024>>>();
    fill_csr_kernel<<<(NEDGE + 255) / 256, 256>>>(esrc, edst);

    // 3 GCN layers (launch 4 = aggregate, launch 5 = GEMM -> ncu target)
    for (int l = 0; l < NLAYER; l++) {
        aggregate_kernel<<<NNODES, 256>>>();
        mma_gemm_kernel<<<dim3(DDIM / 128, NNODES / 128), 256, GEMM_SMEM>>>(
            a_hi, a_lo, wt + (size_t)l * DDIM * DDIM,
            gb + (size_t)l * DDIM, xptr, DDIM, /*relu=*/1);
    }

    // final fc on entity rows only
    split_entity_kernel<<<NENT, 256>>>();
    mma_gemm_kernel<<<dim3(OUTF / 128, NENT / 128), 256, GEMM_SMEM>>>(
        a_hi, a_lo, fcw_h, fcb, out, OUTF, /*relu=*/0);
}

// round 5
// speedup vs baseline: 2.8874x; 1.1352x over previous
#include <cuda_runtime.h>
#include <cuda_fp16.h>
#include <cstdint>

// ---------------- problem constants ----------------
#define NBATCH   128
#define NM       100
#define NE       50
#define NS       25
#define NPB      175
#define NNODES   (NBATCH*NPB)   // 22400
#define HDIM     768
#define TDIM     256
#define DDIM     1024
#define OUTF     768
#define NLAYER   3
#define NEDGE    716800
#define NENT     (NBATCH*NE)    // 6400
#define LRELU    0.01f
#define LN_EPS   1e-5f

// ---------------- device scratch ----------------
__device__ __align__(16) __half  g_xh[(size_t)NNODES * DDIM];   // activations (fp16)
__device__ __align__(16) __half  g_a_hi[(size_t)NNODES * DDIM];
__device__ __align__(16) __half  g_a_lo[(size_t)NNODES * DDIM];
__device__ __align__(16) __half  g_wt[(size_t)NLAYER * DDIM * DDIM];
__device__ __align__(16) __half  g_fcw[(size_t)OUTF * DDIM];
__device__ int   g_deg_out[NNODES];
__device__ int   g_deg_in[NNODES];
__device__ float g_dinv_out[NNODES];
__device__ float g_dinv_in[NNODES];
__device__ int   g_offs[NNODES + 1];
__device__ int   g_cursor[NNODES];
__device__ int   g_col[NEDGE];
__device__ float g_w[NEDGE];

// ---------------- helpers ----------------
__device__ __forceinline__ uint32_t smem_u32(const void* p) {
    uint32_t a;
    asm("{ .reg .u64 t; cvta.to.shared.u64 t, %1; cvt.u32.u64 %0, t; }" : "=r"(a) : "l"(p));
    return a;
}
#define LDSM4(r, addr) \
    asm volatile("ldmatrix.sync.aligned.m8n8.x4.shared.b16 {%0,%1,%2,%3}, [%4];" \
        : "=r"((r)[0]), "=r"((r)[1]), "=r"((r)[2]), "=r"((r)[3]) : "r"(addr))
#define LDSM2(r, addr) \
    asm volatile("ldmatrix.sync.aligned.m8n8.x2.shared.b16 {%0,%1}, [%2];" \
        : "=r"((r)[0]), "=r"((r)[1]) : "r"(addr))
#define MMA16816(d, a, b) \
    asm volatile("mma.sync.aligned.m16n8k16.row.col.f32.f16.f16.f32 " \
        "{%0,%1,%2,%3}, {%4,%5,%6,%7}, {%8,%9}, {%0,%1,%2,%3};" \
        : "+f"((d)[0]), "+f"((d)[1]), "+f"((d)[2]), "+f"((d)[3]) \
        : "r"((a)[0]), "r"((a)[1]), "r"((a)[2]), "r"((a)[3]), "r"((b)[0]), "r"((b)[1]))
#define CP16(dst, src) \
    asm volatile("cp.async.cg.shared.global [%0], [%1], 16;" :: "r"(dst), "l"(src) : "memory")
#define CP_COMMIT() asm volatile("cp.async.commit_group;" ::: "memory")
#define CP_WAIT1()  asm volatile("cp.async.wait_group 1;" ::: "memory")

__device__ __forceinline__ void split4h(float4 v, __half* hi, __half* lo, size_t eidx) {
    __half h[4], l[4];
    float f[4] = {v.x, v.y, v.z, v.w};
#pragma unroll
    for (int k = 0; k < 4; k++) {
        h[k] = __float2half_rn(f[k]);
        l[k] = __float2half_rn(f[k] - __half2float(h[k]));
    }
    *(uint2*)(hi + eidx) = *(uint2*)h;
    *(uint2*)(lo + eidx) = *(uint2*)l;
}

// ---------------- fused prep: build_ln (fp16 out) + zero counters + weight transposes ----------------
#define ZBLKS 88
#define TBLKS (3 * 1024 + 24 * 32)   // 3840

__global__ void __launch_bounds__(256)
fused_prep_kernel(const float* __restrict__ mhs, const float* __restrict__ ehs,
                  const float* __restrict__ shs, const float* __restrict__ temb,
                  const float* __restrict__ scale, const float* __restrict__ bias,
                  const float* __restrict__ gw, const float* __restrict__ fcw) {
    __shared__ float tile[32][33];
    __shared__ float sh1[8], sh2[8], s_mu, s_r;
    int bx = blockIdx.x;
    int t = threadIdx.x;

    if (bx < NNODES) {
        int node = bx;
        int b = node / NPB;
        int i = node - b * NPB;
        int c = t * 4;

        const float* src;
        int type;
        if (i < NM)           { type = 0; src = mhs + ((size_t)b * NM + i) * HDIM; }
        else if (i < NM + NE) { type = 1; src = ehs + ((size_t)b * NE + (i - NM)) * HDIM; }
        else                  { type = 2; src = shs + ((size_t)b * NS + (i - NM - NE)) * HDIM; }

        float4 v;
        if (c < HDIM) v = *(const float4*)(src + c);
        else          v = *(const float4*)(temb + type * TDIM + (c - HDIM));

        float s1 = v.x + v.y + v.z + v.w;
        float s2 = v.x * v.x + v.y * v.y + v.z * v.z + v.w * v.w;
        int lane = t & 31, wid = t >> 5;
#pragma unroll
        for (int o = 16; o > 0; o >>= 1) {
            s1 += __shfl_down_sync(0xFFFFFFFFu, s1, o);
            s2 += __shfl_down_sync(0xFFFFFFFFu, s2, o);
        }
        if (lane == 0) { sh1[wid] = s1; sh2[wid] = s2; }
        __syncthreads();
        if (wid == 0) {
            s1 = (lane < 8) ? sh1[lane] : 0.f;
            s2 = (lane < 8) ? sh2[lane] : 0.f;
#pragma unroll
            for (int o = 4; o > 0; o >>= 1) {
                s1 += __shfl_down_sync(0xFFFFFFFFu, s1, o);
                s2 += __shfl_down_sync(0xFFFFFFFFu, s2, o);
            }
            if (lane == 0) {
                float mu = s1 / (float)DDIM;
                float var = s2 / (float)DDIM - mu * mu;
                s_mu = mu; s_r = rsqrtf(var + LN_EPS);
            }
        }
        __syncthreads();
        float mu = s_mu, r = s_r;
        float4 sc = *(const float4*)(scale + c);
        float4 bi = *(const float4*)(bias + c);
        __half h[4];
        h[0] = __float2half_rn((v.x - mu) * r * sc.x + bi.x);
        h[1] = __float2half_rn((v.y - mu) * r * sc.y + bi.y);
        h[2] = __float2half_rn((v.z - mu) * r * sc.z + bi.z);
        h[3] = __float2half_rn((v.w - mu) * r * sc.w + bi.w);
        *(uint2*)(g_xh + (size_t)node * DDIM + c) = *(uint2*)h;
    } else if (bx < NNODES + ZBLKS) {
        int i = (bx - NNODES) * 256 + t;
        if (i < NNODES) { g_deg_out[i] = 0; g_deg_in[i] = 0; g_cursor[i] = 0; }
    } else {
        int ti = bx - NNODES - ZBLKS;
        const float* in; __half* oh; int R, C, bxx, byy;
        if (ti < 3072) {
            int l = ti >> 10, rr = ti & 1023;
            bxx = rr & 31; byy = rr >> 5;
            in = gw + (size_t)l * DDIM * DDIM;
            oh = g_wt + (size_t)l * DDIM * DDIM;
            R = DDIM; C = DDIM;
        } else {
            int rr = ti - 3072;
            bxx = rr % 24; byy = rr / 24;
            in = fcw; oh = g_fcw; R = DDIM; C = OUTF;
        }
        int c0 = bxx * 32, r0 = byy * 32;
        int x = t & 31, y = t >> 5;
#pragma unroll
        for (int j = 0; j < 32; j += 8)
            tile[y + j][x] = in[(size_t)(r0 + y + j) * C + c0 + x];
        __syncthreads();
#pragma unroll
        for (int j = 0; j < 32; j += 8) {
            float v = tile[x][y + j];
            oh[(size_t)(c0 + y + j) * R + r0 + x] = __float2half_rn(v);
        }
    }
}

// ---------------- graph preprocessing ----------------
__global__ void degree_kernel(const int* __restrict__ esrc, const int* __restrict__ edst) {
    int e = blockIdx.x * blockDim.x + threadIdx.x;
    if (e < NEDGE) { atomicAdd(&g_deg_out[esrc[e]], 1); atomicAdd(&g_deg_in[edst[e]], 1); }
}
__global__ void scan_dinv_kernel() {
    __shared__ int warp_sums[32];
    __shared__ int s_carry;
    int t = threadIdx.x, lane = t & 31, wid = t >> 5;
    if (t == 0) { s_carry = 0; g_offs[0] = 0; }
    __syncthreads();
    for (int base = 0; base < NNODES; base += 1024) {
        int idx = base + t;
        int din = (idx < NNODES) ? g_deg_in[idx] : 0;
        if (idx < NNODES) {
            int dout = g_deg_out[idx]; if (dout < 1) dout = 1;
            int dc = din; if (dc < 1) dc = 1;
            g_dinv_out[idx] = rsqrtf((float)dout);
            g_dinv_in[idx]  = rsqrtf((float)dc);
        }
        int x = din;
#pragma unroll
        for (int o = 1; o < 32; o <<= 1) {
            int y = __shfl_up_sync(0xFFFFFFFFu, x, o);
            if (lane >= o) x += y;
        }
        if (lane == 31) warp_sums[wid] = x;
        __syncthreads();
        if (wid == 0) {
            int ws = warp_sums[lane];
#pragma unroll
            for (int o = 1; o < 32; o <<= 1) {
                int y = __shfl_up_sync(0xFFFFFFFFu, ws, o);
                if (lane >= o) ws += y;
            }
            warp_sums[lane] = ws;
        }
        __syncthreads();
        int incl = x + s_carry + (wid > 0 ? warp_sums[wid - 1] : 0);
        if (idx < NNODES) g_offs[idx + 1] = incl;
        __syncthreads();
        if (t == 1023) s_carry = incl;
        __syncthreads();
    }
}
__global__ void fill_csr_kernel(const int* __restrict__ esrc, const int* __restrict__ edst) {
    int e = blockIdx.x * blockDim.x + threadIdx.x;
    if (e < NEDGE) {
        int s = esrc[e], d = edst[e];
        int pos = g_offs[d] + atomicAdd(&g_cursor[d], 1);
        g_col[pos] = s;
        g_w[pos] = g_dinv_out[s] * g_dinv_in[d];
    }
}

// ---------------- aggregation: gather fp16 x, fp32 accumulate, fp16 hi/lo out ----------------
__global__ void aggregate_kernel() {
    int node = blockIdx.x;
    int t = threadIdx.x;                 // 256 threads, 4 halfs (one uint2) per thread
    int beg = g_offs[node], end = g_offs[node + 1];

    __shared__ int   s_col[256];
    __shared__ float s_w[256];
    const uint2* x2 = (const uint2*)g_xh;   // row pitch = 256 uint2

    float4 acc = make_float4(0.f, 0.f, 0.f, 0.f);
    for (int base = beg; base < end; base += 256) {
        int n = end - base; if (n > 256) n = 256;
        if (t < n) { s_col[t] = g_col[base + t]; s_w[t] = g_w[base + t]; }
        __syncthreads();
#pragma unroll 2
        for (int i = 0; i < n; i++) {
            float ww = s_w[i];
            uint2 u = x2[(size_t)s_col[i] * 256 + t];
            float2 f0 = __half22float2(*(__half2*)&u.x);
            float2 f1 = __half22float2(*(__half2*)&u.y);
            acc.x += ww * f0.x; acc.y += ww * f0.y;
            acc.z += ww * f1.x; acc.w += ww * f1.y;
        }
        __syncthreads();
    }
    split4h(acc, g_a_hi, g_a_lo, (size_t)node * DDIM + t * 4);
}

// ---------------- gather entity rows of g_xh -> packed fp16 (exact; fc is single-pass) ----------------
__global__ void split_entity_kernel() {
    int row = blockIdx.x;
    int b = row / NE, e = row - b * NE;
    int t = threadIdx.x;
    uint2 u = ((const uint2*)g_xh)[(size_t)(b * NPB + NM + e) * 256 + t];
    ((uint2*)g_a_hi)[(size_t)row * 256 + t] = u;
}

// ---------------- HMMA GEMM ----------------
// TWO_PASS: C = act((Ahi+Alo) @ B^T + bias); else C = act(Ahi @ B^T + bias).
// OUT_HALF: C stored fp16 (g_xh), else fp32.
#define BM 128
#define BN 128
#define BK 32
#define SKB 40
#define TILE_E (BM * SKB)                 // 5120 halfs
#define NST 3
#define GEMM_SMEM (NST * 3 * TILE_E * 2)  // 92160 B

template<bool TWO_PASS, bool OUT_HALF>
__global__ void __launch_bounds__(256)
mma_gemm_kernel(const __half* __restrict__ Ahi, const __half* __restrict__ Alo,
                const __half* __restrict__ B, const float* __restrict__ bias,
                void* __restrict__ CoutV, int Nout, int relu) {
    extern __shared__ __half sm[];
    uint32_t sbase = smem_u32(sm);

    const int t = threadIdx.x, lane = t & 31, wid = t >> 5;
    const int wm = wid & 1, wn = wid >> 1;
    const int row0 = blockIdx.y * BM, col0 = blockIdx.x * BN;

    const int r = t >> 1, cpair = (t & 1) * 2;
    const uint4* gAh = (const uint4*)Ahi + (size_t)(row0 + r) * 128;
    const uint4* gAl = (const uint4*)Alo + (size_t)(row0 + r) * 128;
    const uint4* gB  = (const uint4*)B   + (size_t)(col0 + r) * 128;
    const uint32_t so0 = (uint32_t)(r * SKB + cpair * 8) * 2;
    const uint32_t so1 = so0 + 16;

    float acc[4][4][4];
#pragma unroll
    for (int mt = 0; mt < 4; mt++)
#pragma unroll
        for (int nt = 0; nt < 4; nt++)
#pragma unroll
            for (int k = 0; k < 4; k++) acc[mt][nt][k] = 0.f;

    const int nk = 1024 / BK;   // 32

#define ISSUE(k0, st) do { \
        int off = (k0) * 4 + cpair; \
        uint32_t sb_ = sbase + (uint32_t)((st) * 3 * TILE_E * 2); \
        CP16(sb_ + so0, gAh + off); CP16(sb_ + so1, gAh + off + 1); \
        if (TWO_PASS) { CP16(sb_ + TILE_E * 2 + so0, gAl + off); CP16(sb_ + TILE_E * 2 + so1, gAl + off + 1); } \
        CP16(sb_ + 2 * TILE_E * 2 + so0, gB + off); CP16(sb_ + 2 * TILE_E * 2 + so1, gB + off + 1); \
    } while (0)

    ISSUE(0, 0); CP_COMMIT();
    ISSUE(1, 1); CP_COMMIT();

    const int asel = lane >> 3;
    const int arowoff = (asel & 1) * 8 + (lane & 7);
    const int akadd = (asel >> 1) * 8;
    const int browoff = lane & 7;
    const int bkadd = ((lane >> 3) & 1) * 8;

    for (int k0 = 0; k0 < nk; k0++) {
        CP_WAIT1();
        __syncthreads();
        if (k0 + 2 < nk) ISSUE(k0 + 2, (k0 + 2) % 3);
        CP_COMMIT();

        uint32_t base = sbase + (uint32_t)((k0 % 3) * 3 * TILE_E * 2);
        uint32_t bAh = base;
        uint32_t bAl = base + TILE_E * 2;
        uint32_t bB  = base + 2 * TILE_E * 2;
#pragma unroll
        for (int ks = 0; ks < 2; ks++) {
            const int kk = ks * 16;
            uint32_t ah[4][4], al[4][4], bb[4][2];
#pragma unroll
            for (int mt = 0; mt < 4; mt++) {
                int rrow = wm * 64 + mt * 16 + arowoff;
                uint32_t ao = (uint32_t)((rrow * SKB + kk + akadd) * 2);
                LDSM4(ah[mt], bAh + ao);
                if (TWO_PASS) LDSM4(al[mt], bAl + ao);
            }
#pragma unroll
            for (int nt = 0; nt < 4; nt++) {
                int nrow = wn * 32 + nt * 8 + browoff;
                uint32_t bo = (uint32_t)((nrow * SKB + kk + bkadd) * 2);
                LDSM2(bb[nt], bB + bo);
            }
#pragma unroll
            for (int mt = 0; mt < 4; mt++)
#pragma unroll
                for (int nt = 0; nt < 4; nt++) MMA16816(acc[mt][nt], ah[mt], bb[nt]);
            if (TWO_PASS) {
#pragma unroll
                for (int mt = 0; mt < 4; mt++)
#pragma unroll
                    for (int nt = 0; nt < 4; nt++) MMA16816(acc[mt][nt], al[mt], bb[nt]);
            }
        }
        __syncthreads();
    }
#undef ISSUE

    // epilogue
    const int rbase = row0 + wm * 64 + (lane >> 2);
    const int cbase = col0 + wn * 32 + (lane & 3) * 2;
#pragma unroll
    for (int nt = 0; nt < 4; nt++) {
        int col = cbase + nt * 8;
        float b0 = bias[col], b1 = bias[col + 1];
#pragma unroll
        for (int mt = 0; mt < 4; mt++) {
            int rrow = rbase + mt * 16;
            float v0 = acc[mt][nt][0] + b0;
            float v1 = acc[mt][nt][1] + b1;
            float v2 = acc[mt][nt][2] + b0;
            float v3 = acc[mt][nt][3] + b1;
            if (relu) {
                v0 = (v0 > 0.f) ? v0 : LRELU * v0;
                v1 = (v1 > 0.f) ? v1 : LRELU * v1;
                v2 = (v2 > 0.f) ? v2 : LRELU * v2;
                v3 = (v3 > 0.f) ? v3 : LRELU * v3;
            }
            if (OUT_HALF) {
                __half* C = (__half*)CoutV;
                *(__half2*)(C + (size_t)rrow * Nout + col) = __floats2half2_rn(v0, v1);
                *(__half2*)(C + (size_t)(rrow + 8) * Nout + col) = __floats2half2_rn(v2, v3);
            } else {
                float* C = (float*)CoutV;
                *(float2*)(C + (size_t)rrow * Nout + col) = make_float2(v0, v1);
                *(float2*)(C + (size_t)(rrow + 8) * Nout + col) = make_float2(v2, v3);
            }
        }
    }
}

// ---------------- launch ----------------
extern "C" void kernel_launch(void* const* d_in, const int* in_sizes, int n_in,
                              void* d_out, int out_size) {
    const float* mhs  = (const float*)d_in[0];
    const float* ehs  = (const float*)d_in[1];
    const float* shs  = (const float*)d_in[2];
    const int*   esrc = (const int*)d_in[3];
    const int*   edst = (const int*)d_in[4];
    const float* temb = (const float*)d_in[5];
    const float* lns  = (const float*)d_in[6];
    const float* lnb  = (const float*)d_in[7];
    const float* gw   = (const float*)d_in[8];
    const float* gb   = (const float*)d_in[9];
    const float* fcw  = (const float*)d_in[10];
    const float* fcb  = (const float*)d_in[11];
    float* out = (float*)d_out;

    cudaFuncSetAttribute(mma_gemm_kernel<true, true>,
                         cudaFuncAttributeMaxDynamicSharedMemorySize, GEMM_SMEM);
    cudaFuncSetAttribute(mma_gemm_kernel<false, false>,
                         cudaFuncAttributeMaxDynamicSharedMemorySize, GEMM_SMEM);

    __half *wt, *fcw_h, *a_hi, *a_lo, *xh;
    cudaGetSymbolAddress((void**)&wt,    g_wt);
    cudaGetSymbolAddress((void**)&fcw_h, g_fcw);
    cudaGetSymbolAddress((void**)&a_hi,  g_a_hi);
    cudaGetSymbolAddress((void**)&a_lo,  g_a_lo);
    cudaGetSymbolAddress((void**)&xh,    g_xh);

    fused_prep_kernel<<<NNODES + ZBLKS + TBLKS, 256>>>(mhs, ehs, shs, temb, lns, lnb, gw, fcw);
    degree_kernel<<<(NEDGE + 255) / 256, 256>>>(esrc, edst);
    scan_dinv_kernel<<<1, 1024>>>();
    fill_csr_kernel<<<(NEDGE + 255) / 256, 256>>>(esrc, edst);

    for (int l = 0; l < NLAYER; l++) {
        aggregate_kernel<<<NNODES, 256>>>();
        mma_gemm_kernel<true, true><<<dim3(DDIM / 128, NNODES / 128), 256, GEMM_SMEM>>>(
            a_hi, a_lo, wt + (size_t)l * DDIM * DDIM,
            gb + (size_t)l * DDIM, xh, DDIM, /*relu=*/1);
    }

    split_entity_kernel<<<NENT, 256>>>();
    mma_gemm_kernel<false, false><<<dim3(OUTF / 128, NENT / 128), 256, GEMM_SMEM>>>(
        a_hi, a_hi, fcw_h, fcb, out, OUTF, /*relu=*/0);
}

// round 6
// speedup vs baseline: 4.0467x; 1.4015x over previous
#include <cuda_runtime.h>
#include <cuda_fp16.h>
#include <cstdint>

// ---------------- problem constants ----------------
#define NBATCH   128
#define NM       100
#define NE       50
#define NS       25
#define NPB      175
#define NNODES   (NBATCH*NPB)   // 22400
#define HDIM     768
#define TDIM     256
#define DDIM     1024
#define OUTF     768
#define NLAYER   3
#define NEDGE    716800
#define NENT     (NBATCH*NE)    // 6400
#define LRELU    0.01f
#define LN_EPS   1e-5f

// ---------------- device scratch ----------------
__device__ __align__(16) __half  g_xh[(size_t)NNODES * DDIM];   // activations (fp16)
__device__ __align__(16) __half  g_ah[(size_t)NNODES * DDIM];   // aggregated features (fp16)
__device__ __align__(16) __half  g_wt[(size_t)NLAYER * DDIM * DDIM];
__device__ __align__(16) __half  g_fcw[(size_t)OUTF * DDIM];
__device__ int   g_deg_out[NNODES];
__device__ int   g_deg_in[NNODES];
__device__ float g_dinv_out[NNODES];
__device__ float g_dinv_in[NNODES];
__device__ int   g_offs[NNODES + 1];
__device__ int   g_cursor[NNODES];
__device__ int   g_col[NEDGE];
__device__ float g_w[NEDGE];

// ---------------- helpers ----------------
__device__ __forceinline__ uint32_t smem_u32(const void* p) {
    uint32_t a;
    asm("{ .reg .u64 t; cvta.to.shared.u64 t, %1; cvt.u32.u64 %0, t; }" : "=r"(a) : "l"(p));
    return a;
}
#define LDSM4(r, addr) \
    asm volatile("ldmatrix.sync.aligned.m8n8.x4.shared.b16 {%0,%1,%2,%3}, [%4];" \
        : "=r"((r)[0]), "=r"((r)[1]), "=r"((r)[2]), "=r"((r)[3]) : "r"(addr))
#define LDSM2(r, addr) \
    asm volatile("ldmatrix.sync.aligned.m8n8.x2.shared.b16 {%0,%1}, [%2];" \
        : "=r"((r)[0]), "=r"((r)[1]) : "r"(addr))
#define MMA16816(d, a, b) \
    asm volatile("mma.sync.aligned.m16n8k16.row.col.f32.f16.f16.f32 " \
        "{%0,%1,%2,%3}, {%4,%5,%6,%7}, {%8,%9}, {%0,%1,%2,%3};" \
        : "+f"((d)[0]), "+f"((d)[1]), "+f"((d)[2]), "+f"((d)[3]) \
        : "r"((a)[0]), "r"((a)[1]), "r"((a)[2]), "r"((a)[3]), "r"((b)[0]), "r"((b)[1]))
#define CP16(dst, src) \
    asm volatile("cp.async.cg.shared.global [%0], [%1], 16;" :: "r"(dst), "l"(src) : "memory")
#define CP_COMMIT() asm volatile("cp.async.commit_group;" ::: "memory")
#define CP_WAIT1()  asm volatile("cp.async.wait_group 1;" ::: "memory")

// ---------------- fused prep: build_ln (fp16 out) + zero counters + weight transposes ----------------
#define ZBLKS 88
#define TBLKS (3 * 1024 + 24 * 32)   // 3840

__global__ void __launch_bounds__(256)
fused_prep_kernel(const float* __restrict__ mhs, const float* __restrict__ ehs,
                  const float* __restrict__ shs, const float* __restrict__ temb,
                  const float* __restrict__ scale, const float* __restrict__ bias,
                  const float* __restrict__ gw, const float* __restrict__ fcw) {
    __shared__ float tile[32][33];
    __shared__ float sh1[8], sh2[8], s_mu, s_r;
    int bx = blockIdx.x;
    int t = threadIdx.x;

    if (bx < NNODES) {
        int node = bx;
        int b = node / NPB;
        int i = node - b * NPB;
        int c = t * 4;

        const float* src;
        int type;
        if (i < NM)           { type = 0; src = mhs + ((size_t)b * NM + i) * HDIM; }
        else if (i < NM + NE) { type = 1; src = ehs + ((size_t)b * NE + (i - NM)) * HDIM; }
        else                  { type = 2; src = shs + ((size_t)b * NS + (i - NM - NE)) * HDIM; }

        float4 v;
        if (c < HDIM) v = *(const float4*)(src + c);
        else          v = *(const float4*)(temb + type * TDIM + (c - HDIM));

        float s1 = v.x + v.y + v.z + v.w;
        float s2 = v.x * v.x + v.y * v.y + v.z * v.z + v.w * v.w;
        int lane = t & 31, wid = t >> 5;
#pragma unroll
        for (int o = 16; o > 0; o >>= 1) {
            s1 += __shfl_down_sync(0xFFFFFFFFu, s1, o);
            s2 += __shfl_down_sync(0xFFFFFFFFu, s2, o);
        }
        if (lane == 0) { sh1[wid] = s1; sh2[wid] = s2; }
        __syncthreads();
        if (wid == 0) {
            s1 = (lane < 8) ? sh1[lane] : 0.f;
            s2 = (lane < 8) ? sh2[lane] : 0.f;
#pragma unroll
            for (int o = 4; o > 0; o >>= 1) {
                s1 += __shfl_down_sync(0xFFFFFFFFu, s1, o);
                s2 += __shfl_down_sync(0xFFFFFFFFu, s2, o);
            }
            if (lane == 0) {
                float mu = s1 / (float)DDIM;
                float var = s2 / (float)DDIM - mu * mu;
                s_mu = mu; s_r = rsqrtf(var + LN_EPS);
            }
        }
        __syncthreads();
        float mu = s_mu, r = s_r;
        float4 sc = *(const float4*)(scale + c);
        float4 bi = *(const float4*)(bias + c);
        __half h[4];
        h[0] = __float2half_rn((v.x - mu) * r * sc.x + bi.x);
        h[1] = __float2half_rn((v.y - mu) * r * sc.y + bi.y);
        h[2] = __float2half_rn((v.z - mu) * r * sc.z + bi.z);
        h[3] = __float2half_rn((v.w - mu) * r * sc.w + bi.w);
        *(uint2*)(g_xh + (size_t)node * DDIM + c) = *(uint2*)h;
    } else if (bx < NNODES + ZBLKS) {
        int i = (bx - NNODES) * 256 + t;
        if (i < NNODES) { g_deg_out[i] = 0; g_deg_in[i] = 0; g_cursor[i] = 0; }
    } else {
        int ti = bx - NNODES - ZBLKS;
        const float* in; __half* oh; int R, C, bxx, byy;
        if (ti < 3072) {
            int l = ti >> 10, rr = ti & 1023;
            bxx = rr & 31; byy = rr >> 5;
            in = gw + (size_t)l * DDIM * DDIM;
            oh = g_wt + (size_t)l * DDIM * DDIM;
            R = DDIM; C = DDIM;
        } else {
            int rr = ti - 3072;
            bxx = rr % 24; byy = rr / 24;
            in = fcw; oh = g_fcw; R = DDIM; C = OUTF;
        }
        int c0 = bxx * 32, r0 = byy * 32;
        int x = t & 31, y = t >> 5;
#pragma unroll
        for (int j = 0; j < 32; j += 8)
            tile[y + j][x] = in[(size_t)(r0 + y + j) * C + c0 + x];
        __syncthreads();
#pragma unroll
        for (int j = 0; j < 32; j += 8) {
            float v = tile[x][y + j];
            oh[(size_t)(c0 + y + j) * R + r0 + x] = __float2half_rn(v);
        }
    }
}

// ---------------- graph preprocessing ----------------
__global__ void degree_kernel(const int* __restrict__ esrc, const int* __restrict__ edst) {
    int e = blockIdx.x * blockDim.x + threadIdx.x;
    if (e < NEDGE) { atomicAdd(&g_deg_out[esrc[e]], 1); atomicAdd(&g_deg_in[edst[e]], 1); }
}
__global__ void scan_dinv_kernel() {
    __shared__ int warp_sums[32];
    __shared__ int s_carry;
    int t = threadIdx.x, lane = t & 31, wid = t >> 5;
    if (t == 0) { s_carry = 0; g_offs[0] = 0; }
    __syncthreads();
    for (int base = 0; base < NNODES; base += 1024) {
        int idx = base + t;
        int din = (idx < NNODES) ? g_deg_in[idx] : 0;
        if (idx < NNODES) {
            int dout = g_deg_out[idx]; if (dout < 1) dout = 1;
            int dc = din; if (dc < 1) dc = 1;
            g_dinv_out[idx] = rsqrtf((float)dout);
            g_dinv_in[idx]  = rsqrtf((float)dc);
        }
        int x = din;
#pragma unroll
        for (int o = 1; o < 32; o <<= 1) {
            int y = __shfl_up_sync(0xFFFFFFFFu, x, o);
            if (lane >= o) x += y;
        }
        if (lane == 31) warp_sums[wid] = x;
        __syncthreads();
        if (wid == 0) {
            int ws = warp_sums[lane];
#pragma unroll
            for (int o = 1; o < 32; o <<= 1) {
                int y = __shfl_up_sync(0xFFFFFFFFu, ws, o);
                if (lane >= o) ws += y;
            }
            warp_sums[lane] = ws;
        }
        __syncthreads();
        int incl = x + s_carry + (wid > 0 ? warp_sums[wid - 1] : 0);
        if (idx < NNODES) g_offs[idx + 1] = incl;
        __syncthreads();
        if (t == 1023) s_carry = incl;
        __syncthreads();
    }
}
__global__ void fill_csr_kernel(const int* __restrict__ esrc, const int* __restrict__ edst) {
    int e = blockIdx.x * blockDim.x + threadIdx.x;
    if (e < NEDGE) {
        int s = esrc[e], d = edst[e];
        int pos = g_offs[d] + atomicAdd(&g_cursor[d], 1);
        g_col[pos] = s;
        g_w[pos] = g_dinv_out[s] * g_dinv_in[d];
    }
}

// ---------------- aggregation: gather fp16 x, fp32 accumulate, fp16 out ----------------
__global__ void aggregate_kernel() {
    int node = blockIdx.x;
    int t = threadIdx.x;                 // 256 threads, 4 halfs (one uint2) per thread
    int beg = g_offs[node], end = g_offs[node + 1];

    __shared__ int   s_col[256];
    __shared__ float s_w[256];
    const uint2* x2 = (const uint2*)g_xh;   // row pitch = 256 uint2

    float4 acc = make_float4(0.f, 0.f, 0.f, 0.f);
    for (int base = beg; base < end; base += 256) {
        int n = end - base; if (n > 256) n = 256;
        if (t < n) { s_col[t] = g_col[base + t]; s_w[t] = g_w[base + t]; }
        __syncthreads();
#pragma unroll 4
        for (int i = 0; i < n; i++) {
            float ww = s_w[i];
            uint2 u = x2[(size_t)s_col[i] * 256 + t];
            float2 f0 = __half22float2(*(__half2*)&u.x);
            float2 f1 = __half22float2(*(__half2*)&u.y);
            acc.x += ww * f0.x; acc.y += ww * f0.y;
            acc.z += ww * f1.x; acc.w += ww * f1.y;
        }
        __syncthreads();
    }
    __half h[4];
    h[0] = __float2half_rn(acc.x);
    h[1] = __float2half_rn(acc.y);
    h[2] = __float2half_rn(acc.z);
    h[3] = __float2half_rn(acc.w);
    *(uint2*)(g_ah + (size_t)node * DDIM + t * 4) = *(uint2*)h;
}

// ---------------- HMMA fp16 single-pass GEMM ----------------
// C = act(A @ B^T + bias); A fp16 [M x 1024] (row-mapped if ROWMAP), B fp16 [Nout x 1024].
// CTA 128x128, BK=32, 256 thr / 8 warps (2x4), warp tile 64x32, 3-stage cp.async.
#define BM 128
#define BN 128
#define BK 32
#define SKB 40
#define TILE_E (BM * SKB)                 // 5120 halfs = 10240 B
#define NST 3
#define GEMM_SMEM (NST * 2 * TILE_E * 2)  // 61440 B

template<bool ROWMAP, bool OUT_HALF>
__global__ void __launch_bounds__(256)
mma_gemm_kernel(const __half* __restrict__ A, const __half* __restrict__ B,
                const float* __restrict__ bias, void* __restrict__ CoutV,
                int Nout, int relu) {
    extern __shared__ __half sm[];
    uint32_t sbase = smem_u32(sm);

    const int t = threadIdx.x, lane = t & 31, wid = t >> 5;
    const int wm = wid & 1, wn = wid >> 1;
    const int row0 = blockIdx.y * BM, col0 = blockIdx.x * BN;

    const int r = t >> 1, cpair = (t & 1) * 2;
    int gr = row0 + r;
    int srow = ROWMAP ? ((gr / NE) * NPB + NM + (gr % NE)) : gr;
    const uint4* gA = (const uint4*)A + (size_t)srow * 128;      // row pitch: 1024 halfs
    const uint4* gB = (const uint4*)B + (size_t)(col0 + r) * 128;
    const uint32_t so0 = (uint32_t)(r * SKB + cpair * 8) * 2;    // bytes
    const uint32_t so1 = so0 + 16;

    float acc[4][4][4];
#pragma unroll
    for (int mt = 0; mt < 4; mt++)
#pragma unroll
        for (int nt = 0; nt < 4; nt++)
#pragma unroll
            for (int k = 0; k < 4; k++) acc[mt][nt][k] = 0.f;

    const int nk = 1024 / BK;   // 32

#define ISSUE(k0, st) do { \
        int off = (k0) * 4 + cpair; \
        uint32_t sb_ = sbase + (uint32_t)((st) * 2 * TILE_E * 2); \
        CP16(sb_ + so0, gA + off); CP16(sb_ + so1, gA + off + 1); \
        CP16(sb_ + TILE_E * 2 + so0, gB + off); CP16(sb_ + TILE_E * 2 + so1, gB + off + 1); \
    } while (0)

    ISSUE(0, 0); CP_COMMIT();
    ISSUE(1, 1); CP_COMMIT();

    const int asel = lane >> 3;
    const int arowoff = (asel & 1) * 8 + (lane & 7);
    const int akadd = (asel >> 1) * 8;
    const int browoff = lane & 7;
    const int bkadd = ((lane >> 3) & 1) * 8;

    for (int k0 = 0; k0 < nk; k0++) {
        CP_WAIT1();
        __syncthreads();
        if (k0 + 2 < nk) ISSUE(k0 + 2, (k0 + 2) % 3);
        CP_COMMIT();

        uint32_t base = sbase + (uint32_t)((k0 % 3) * 2 * TILE_E * 2);
        uint32_t bA = base;
        uint32_t bB = base + TILE_E * 2;
#pragma unroll
        for (int ks = 0; ks < 2; ks++) {
            const int kk = ks * 16;
            uint32_t ah[4][4], bb[4][2];
#pragma unroll
            for (int mt = 0; mt < 4; mt++) {
                int rrow = wm * 64 + mt * 16 + arowoff;
                LDSM4(ah[mt], bA + (uint32_t)((rrow * SKB + kk + akadd) * 2));
            }
#pragma unroll
            for (int nt = 0; nt < 4; nt++) {
                int nrow = wn * 32 + nt * 8 + browoff;
                LDSM2(bb[nt], bB + (uint32_t)((nrow * SKB + kk + bkadd) * 2));
            }
#pragma unroll
            for (int mt = 0; mt < 4; mt++)
#pragma unroll
                for (int nt = 0; nt < 4; nt++) MMA16816(acc[mt][nt], ah[mt], bb[nt]);
        }
        __syncthreads();
    }
#undef ISSUE

    // epilogue
    const int rbase = row0 + wm * 64 + (lane >> 2);
    const int cbase = col0 + wn * 32 + (lane & 3) * 2;
#pragma unroll
    for (int nt = 0; nt < 4; nt++) {
        int col = cbase + nt * 8;
        float b0 = bias[col], b1 = bias[col + 1];
#pragma unroll
        for (int mt = 0; mt < 4; mt++) {
            int rrow = rbase + mt * 16;
            float v0 = acc[mt][nt][0] + b0;
            float v1 = acc[mt][nt][1] + b1;
            float v2 = acc[mt][nt][2] + b0;
            float v3 = acc[mt][nt][3] + b1;
            if (relu) {
                v0 = (v0 > 0.f) ? v0 : LRELU * v0;
                v1 = (v1 > 0.f) ? v1 : LRELU * v1;
                v2 = (v2 > 0.f) ? v2 : LRELU * v2;
                v3 = (v3 > 0.f) ? v3 : LRELU * v3;
            }
            if (OUT_HALF) {
                __half* C = (__half*)CoutV;
                *(__half2*)(C + (size_t)rrow * Nout + col) = __floats2half2_rn(v0, v1);
                *(__half2*)(C + (size_t)(rrow + 8) * Nout + col) = __floats2half2_rn(v2, v3);
            } else {
                float* C = (float*)CoutV;
                *(float2*)(C + (size_t)rrow * Nout + col) = make_float2(v0, v1);
                *(float2*)(C + (size_t)(rrow + 8) * Nout + col) = make_float2(v2, v3);
            }
        }
    }
}

// ---------------- launch ----------------
extern "C" void kernel_launch(void* const* d_in, const int* in_sizes, int n_in,
                              void* d_out, int out_size) {
    const float* mhs  = (const float*)d_in[0];
    const float* ehs  = (const float*)d_in[1];
    const float* shs  = (const float*)d_in[2];
    const int*   esrc = (const int*)d_in[3];
    const int*   edst = (const int*)d_in[4];
    const float* temb = (const float*)d_in[5];
    const float* lns  = (const float*)d_in[6];
    const float* lnb  = (const float*)d_in[7];
    const float* gw   = (const float*)d_in[8];
    const float* gb   = (const float*)d_in[9];
    const float* fcw  = (const float*)d_in[10];
    const float* fcb  = (const float*)d_in[11];
    float* out = (float*)d_out;

    cudaFuncSetAttribute(mma_gemm_kernel<false, true>,
                         cudaFuncAttributeMaxDynamicSharedMemorySize, GEMM_SMEM);
    cudaFuncSetAttribute(mma_gemm_kernel<true, false>,
                         cudaFuncAttributeMaxDynamicSharedMemorySize, GEMM_SMEM);

    __half *wt, *fcw_h, *ah, *xh;
    cudaGetSymbolAddress((void**)&wt,    g_wt);
    cudaGetSymbolAddress((void**)&fcw_h, g_fcw);
    cudaGetSymbolAddress((void**)&ah,    g_ah);
    cudaGetSymbolAddress((void**)&xh,    g_xh);

    fused_prep_kernel<<<NNODES + ZBLKS + TBLKS, 256>>>(mhs, ehs, shs, temb, lns, lnb, gw, fcw);
    degree_kernel<<<(NEDGE + 255) / 256, 256>>>(esrc, edst);
    scan_dinv_kernel<<<1, 1024>>>();
    fill_csr_kernel<<<(NEDGE + 255) / 256, 256>>>(esrc, edst);

    for (int l = 0; l < NLAYER; l++) {
        aggregate_kernel<<<NNODES, 256>>>();
        mma_gemm_kernel<false, true><<<dim3(DDIM / 128, NNODES / 128), 256, GEMM_SMEM>>>(
            ah, wt + (size_t)l * DDIM * DDIM, gb + (size_t)l * DDIM, xh, DDIM, /*relu=*/1);
    }

    // fc on entity rows only, gathered directly from g_xh via ROWMAP
    mma_gemm_kernel<true, false><<<dim3(OUTF / 128, NENT / 128), 256, GEMM_SMEM>>>(
        xh, fcw_h, fcb, out, OUTF, /*relu=*/0);
}

// round 7
// speedup vs baseline: 4.9081x; 1.2129x over previous
#include <cuda_runtime.h>
#include <cuda_fp16.h>
#include <cstdint>

// ---------------- problem constants ----------------
#define NBATCH   128
#define NM       100
#define NE       50
#define NS       25
#define NPB      175
#define NNODES   (NBATCH*NPB)   // 22400
#define HDIM     768
#define TDIM     256
#define DDIM     1024
#define OUTF     768
#define NLAYER   3
#define NEDGE    716800
#define NENT     (NBATCH*NE)    // 6400
#define LRELU    0.01f
#define LN_EPS   1e-5f

// ---------------- device scratch ----------------
__device__ __align__(16) __half  g_xh[(size_t)NNODES * DDIM];   // activations (fp16)
__device__ __align__(16) __half  g_ah[(size_t)NNODES * DDIM];   // aggregated features (fp16)
__device__ __align__(16) __half  g_wt[(size_t)NLAYER * DDIM * DDIM];
__device__ __align__(16) __half  g_fcw[(size_t)OUTF * DDIM];
__device__ int   g_deg_out[NNODES];
__device__ int   g_deg_in[NNODES];
__device__ float g_dinv_out[NNODES];
__device__ float g_dinv_in[NNODES];
__device__ int   g_offs[NNODES + 1];
__device__ int   g_cursor[NNODES];
__device__ int   g_col[NEDGE];
__device__ float g_w[NEDGE];

// ---------------- helpers ----------------
__device__ __forceinline__ uint32_t smem_u32(const void* p) {
    uint32_t a;
    asm("{ .reg .u64 t; cvta.to.shared.u64 t, %1; cvt.u32.u64 %0, t; }" : "=r"(a) : "l"(p));
    return a;
}
#define LDSM4(r, addr) \
    asm volatile("ldmatrix.sync.aligned.m8n8.x4.shared.b16 {%0,%1,%2,%3}, [%4];" \
        : "=r"((r)[0]), "=r"((r)[1]), "=r"((r)[2]), "=r"((r)[3]) : "r"(addr))
#define LDSM2(r, addr) \
    asm volatile("ldmatrix.sync.aligned.m8n8.x2.shared.b16 {%0,%1}, [%2];" \
        : "=r"((r)[0]), "=r"((r)[1]) : "r"(addr))
#define MMA16816(d, a, b) \
    asm volatile("mma.sync.aligned.m16n8k16.row.col.f32.f16.f16.f32 " \
        "{%0,%1,%2,%3}, {%4,%5,%6,%7}, {%8,%9}, {%0,%1,%2,%3};" \
        : "+f"((d)[0]), "+f"((d)[1]), "+f"((d)[2]), "+f"((d)[3]) \
        : "r"((a)[0]), "r"((a)[1]), "r"((a)[2]), "r"((a)[3]), "r"((b)[0]), "r"((b)[1]))
#define CP16(dst, src) \
    asm volatile("cp.async.cg.shared.global [%0], [%1], 16;" :: "r"(dst), "l"(src) : "memory")
#define CP_COMMIT() asm volatile("cp.async.commit_group;" ::: "memory")
#define CP_WAIT1()  asm volatile("cp.async.wait_group 1;" ::: "memory")

// ---------------- fused prep: build_ln (fp16 out) + zero counters + weight transposes ----------------
#define ZBLKS 88
#define TBLKS (3 * 1024 + 24 * 32)   // 3840

__global__ void __launch_bounds__(256)
fused_prep_kernel(const float* __restrict__ mhs, const float* __restrict__ ehs,
                  const float* __restrict__ shs, const float* __restrict__ temb,
                  const float* __restrict__ scale, const float* __restrict__ bias,
                  const float* __restrict__ gw, const float* __restrict__ fcw) {
    __shared__ float tile[32][33];
    __shared__ float sh1[8], sh2[8], s_mu, s_r;
    int bx = blockIdx.x;
    int t = threadIdx.x;

    if (bx < NNODES) {
        int node = bx;
        int b = node / NPB;
        int i = node - b * NPB;
        int c = t * 4;

        const float* src;
        int type;
        if (i < NM)           { type = 0; src = mhs + ((size_t)b * NM + i) * HDIM; }
        else if (i < NM + NE) { type = 1; src = ehs + ((size_t)b * NE + (i - NM)) * HDIM; }
        else                  { type = 2; src = shs + ((size_t)b * NS + (i - NM - NE)) * HDIM; }

        float4 v;
        if (c < HDIM) v = *(const float4*)(src + c);
        else          v = *(const float4*)(temb + type * TDIM + (c - HDIM));

        float s1 = v.x + v.y + v.z + v.w;
        float s2 = v.x * v.x + v.y * v.y + v.z * v.z + v.w * v.w;
        int lane = t & 31, wid = t >> 5;
#pragma unroll
        for (int o = 16; o > 0; o >>= 1) {
            s1 += __shfl_down_sync(0xFFFFFFFFu, s1, o);
            s2 += __shfl_down_sync(0xFFFFFFFFu, s2, o);
        }
        if (lane == 0) { sh1[wid] = s1; sh2[wid] = s2; }
        __syncthreads();
        if (wid == 0) {
            s1 = (lane < 8) ? sh1[lane] : 0.f;
            s2 = (lane < 8) ? sh2[lane] : 0.f;
#pragma unroll
            for (int o = 4; o > 0; o >>= 1) {
                s1 += __shfl_down_sync(0xFFFFFFFFu, s1, o);
                s2 += __shfl_down_sync(0xFFFFFFFFu, s2, o);
            }
            if (lane == 0) {
                float mu = s1 / (float)DDIM;
                float var = s2 / (float)DDIM - mu * mu;
                s_mu = mu; s_r = rsqrtf(var + LN_EPS);
            }
        }
        __syncthreads();
        float mu = s_mu, r = s_r;
        float4 sc = *(const float4*)(scale + c);
        float4 bi = *(const float4*)(bias + c);
        __half h[4];
        h[0] = __float2half_rn((v.x - mu) * r * sc.x + bi.x);
        h[1] = __float2half_rn((v.y - mu) * r * sc.y + bi.y);
        h[2] = __float2half_rn((v.z - mu) * r * sc.z + bi.z);
        h[3] = __float2half_rn((v.w - mu) * r * sc.w + bi.w);
        *(uint2*)(g_xh + (size_t)node * DDIM + c) = *(uint2*)h;
    } else if (bx < NNODES + ZBLKS) {
        int i = (bx - NNODES) * 256 + t;
        if (i < NNODES) { g_deg_out[i] = 0; g_deg_in[i] = 0; g_cursor[i] = 0; }
    } else {
        int ti = bx - NNODES - ZBLKS;
        const float* in; __half* oh; int R, C, bxx, byy;
        if (ti < 3072) {
            int l = ti >> 10, rr = ti & 1023;
            bxx = rr & 31; byy = rr >> 5;
            in = gw + (size_t)l * DDIM * DDIM;
            oh = g_wt + (size_t)l * DDIM * DDIM;
            R = DDIM; C = DDIM;
        } else {
            int rr = ti - 3072;
            bxx = rr % 24; byy = rr / 24;
            in = fcw; oh = g_fcw; R = DDIM; C = OUTF;
        }
        int c0 = bxx * 32, r0 = byy * 32;
        int x = t & 31, y = t >> 5;
#pragma unroll
        for (int j = 0; j < 32; j += 8)
            tile[y + j][x] = in[(size_t)(r0 + y + j) * C + c0 + x];
        __syncthreads();
#pragma unroll
        for (int j = 0; j < 32; j += 8) {
            float v = tile[x][y + j];
            oh[(size_t)(c0 + y + j) * R + r0 + x] = __float2half_rn(v);
        }
    }
}

// ---------------- graph preprocessing ----------------
__global__ void degree_kernel(const int* __restrict__ esrc, const int* __restrict__ edst) {
    int e = blockIdx.x * blockDim.x + threadIdx.x;
    if (e < NEDGE) { atomicAdd(&g_deg_out[esrc[e]], 1); atomicAdd(&g_deg_in[edst[e]], 1); }
}

// single-pass scan: 1024 threads x 22 contiguous elements each, one block-scan
#define SCAN_PER 22
__global__ void __launch_bounds__(1024) scan_dinv_kernel() {
    __shared__ int warp_sums[32];
    int t = threadIdx.x, lane = t & 31, wid = t >> 5;
    int i0 = t * SCAN_PER;

    int deg[SCAN_PER];
    int run = 0;
#pragma unroll
    for (int j = 0; j < SCAN_PER; j++) {
        int idx = i0 + j;
        int din = (idx < NNODES) ? g_deg_in[idx] : 0;
        if (idx < NNODES) {
            int dout = g_deg_out[idx]; if (dout < 1) dout = 1;
            int dc = din; if (dc < 1) dc = 1;
            g_dinv_out[idx] = rsqrtf((float)dout);
            g_dinv_in[idx]  = rsqrtf((float)dc);
        }
        run += din;
        deg[j] = run;            // local inclusive prefix
    }

    // block-exclusive scan of per-thread totals
    int x = run;
#pragma unroll
    for (int o = 1; o < 32; o <<= 1) {
        int y = __shfl_up_sync(0xFFFFFFFFu, x, o);
        if (lane >= o) x += y;
    }
    if (lane == 31) warp_sums[wid] = x;
    __syncthreads();
    if (wid == 0) {
        int ws = warp_sums[lane];
#pragma unroll
        for (int o = 1; o < 32; o <<= 1) {
            int y = __shfl_up_sync(0xFFFFFFFFu, ws, o);
            if (lane >= o) ws += y;
        }
        warp_sums[lane] = ws;
    }
    __syncthreads();
    int excl = (x - run) + (wid > 0 ? warp_sums[wid - 1] : 0);

    if (t == 0) g_offs[0] = 0;
#pragma unroll
    for (int j = 0; j < SCAN_PER; j++) {
        int idx = i0 + j;
        if (idx < NNODES) g_offs[idx + 1] = excl + deg[j];
    }
}

__global__ void fill_csr_kernel(const int* __restrict__ esrc, const int* __restrict__ edst) {
    int e = blockIdx.x * blockDim.x + threadIdx.x;
    if (e < NEDGE) {
        int s = esrc[e], d = edst[e];
        int pos = g_offs[d] + atomicAdd(&g_cursor[d], 1);
        g_col[pos] = s;
        g_w[pos] = g_dinv_out[s] * g_dinv_in[d];
    }
}

// ---------------- aggregation: gather fp16 x, fp32 accumulate, fp16 out ----------------
// ENT_ONLY: only entity dst nodes (layer 3); output written compactly at blockIdx row.
template<bool ENT_ONLY>
__global__ void aggregate_kernel() {
    int orow = blockIdx.x;
    int node = ENT_ONLY ? ((orow / NE) * NPB + NM + (orow % NE)) : orow;
    int t = threadIdx.x;                 // 256 threads, 4 halfs (one uint2) each
    int beg = g_offs[node], end = g_offs[node + 1];

    __shared__ int   s_col[256];
    __shared__ float s_w[256];
    const uint2* x2 = (const uint2*)g_xh;   // row pitch = 256 uint2

    float4 acc = make_float4(0.f, 0.f, 0.f, 0.f);
    for (int base = beg; base < end; base += 256) {
        int n = end - base; if (n > 256) n = 256;
        if (t < n) { s_col[t] = g_col[base + t]; s_w[t] = g_w[base + t]; }
        __syncthreads();
#pragma unroll 4
        for (int i = 0; i < n; i++) {
            float ww = s_w[i];
            uint2 u = x2[(size_t)s_col[i] * 256 + t];
            float2 f0 = __half22float2(*(__half2*)&u.x);
            float2 f1 = __half22float2(*(__half2*)&u.y);
            acc.x += ww * f0.x; acc.y += ww * f0.y;
            acc.z += ww * f1.x; acc.w += ww * f1.y;
        }
        __syncthreads();
    }
    __half h[4];
    h[0] = __float2half_rn(acc.x);
    h[1] = __float2half_rn(acc.y);
    h[2] = __float2half_rn(acc.z);
    h[3] = __float2half_rn(acc.w);
    *(uint2*)(g_ah + (size_t)orow * DDIM + t * 4) = *(uint2*)h;
}

// ---------------- HMMA fp16 single-pass GEMM ----------------
// C = act(A @ B^T + bias); A fp16 [M x 1024], B fp16 [Nout x 1024].
#define BM 128
#define BN 128
#define BK 32
#define SKB 40
#define TILE_E (BM * SKB)                 // 5120 halfs = 10240 B
#define NST 3
#define GEMM_SMEM (NST * 2 * TILE_E * 2)  // 61440 B

template<bool OUT_HALF>
__global__ void __launch_bounds__(256)
mma_gemm_kernel(const __half* __restrict__ A, const __half* __restrict__ B,
                const float* __restrict__ bias, void* __restrict__ CoutV,
                int Nout, int relu) {
    extern __shared__ __half sm[];
    uint32_t sbase = smem_u32(sm);

    const int t = threadIdx.x, lane = t & 31, wid = t >> 5;
    const int wm = wid & 1, wn = wid >> 1;
    const int row0 = blockIdx.y * BM, col0 = blockIdx.x * BN;

    const int r = t >> 1, cpair = (t & 1) * 2;
    const uint4* gA = (const uint4*)A + (size_t)(row0 + r) * 128;  // row pitch: 1024 halfs
    const uint4* gB = (const uint4*)B + (size_t)(col0 + r) * 128;
    const uint32_t so0 = (uint32_t)(r * SKB + cpair * 8) * 2;
    const uint32_t so1 = so0 + 16;

    float acc[4][4][4];
#pragma unroll
    for (int mt = 0; mt < 4; mt++)
#pragma unroll
        for (int nt = 0; nt < 4; nt++)
#pragma unroll
            for (int k = 0; k < 4; k++) acc[mt][nt][k] = 0.f;

    const int nk = 1024 / BK;   // 32

#define ISSUE(k0, st) do { \
        int off = (k0) * 4 + cpair; \
        uint32_t sb_ = sbase + (uint32_t)((st) * 2 * TILE_E * 2); \
        CP16(sb_ + so0, gA + off); CP16(sb_ + so1, gA + off + 1); \
        CP16(sb_ + TILE_E * 2 + so0, gB + off); CP16(sb_ + TILE_E * 2 + so1, gB + off + 1); \
    } while (0)

    ISSUE(0, 0); CP_COMMIT();
    ISSUE(1, 1); CP_COMMIT();

    const int asel = lane >> 3;
    const int arowoff = (asel & 1) * 8 + (lane & 7);
    const int akadd = (asel >> 1) * 8;
    const int browoff = lane & 7;
    const int bkadd = ((lane >> 3) & 1) * 8;

    for (int k0 = 0; k0 < nk; k0++) {
        CP_WAIT1();
        __syncthreads();
        if (k0 + 2 < nk) ISSUE(k0 + 2, (k0 + 2) % 3);
        CP_COMMIT();

        uint32_t base = sbase + (uint32_t)((k0 % 3) * 2 * TILE_E * 2);
        uint32_t bA = base;
        uint32_t bB = base + TILE_E * 2;
#pragma unroll
        for (int ks = 0; ks < 2; ks++) {
            const int kk = ks * 16;
            uint32_t ah[4][4], bb[4][2];
#pragma unroll
            for (int mt = 0; mt < 4; mt++) {
                int rrow = wm * 64 + mt * 16 + arowoff;
                LDSM4(ah[mt], bA + (uint32_t)((rrow * SKB + kk + akadd) * 2));
            }
#pragma unroll
            for (int nt = 0; nt < 4; nt++) {
                int nrow = wn * 32 + nt * 8 + browoff;
                LDSM2(bb[nt], bB + (uint32_t)((nrow * SKB + kk + bkadd) * 2));
            }
#pragma unroll
            for (int mt = 0; mt < 4; mt++)
#pragma unroll
                for (int nt = 0; nt < 4; nt++) MMA16816(acc[mt][nt], ah[mt], bb[nt]);
        }
        __syncthreads();
    }
#undef ISSUE

    // epilogue
    const int rbase = row0 + wm * 64 + (lane >> 2);
    const int cbase = col0 + wn * 32 + (lane & 3) * 2;
#pragma unroll
    for (int nt = 0; nt < 4; nt++) {
        int col = cbase + nt * 8;
        float b0 = bias[col], b1 = bias[col + 1];
#pragma unroll
        for (int mt = 0; mt < 4; mt++) {
            int rrow = rbase + mt * 16;
            float v0 = acc[mt][nt][0] + b0;
            float v1 = acc[mt][nt][1] + b1;
            float v2 = acc[mt][nt][2] + b0;
            float v3 = acc[mt][nt][3] + b1;
            if (relu) {
                v0 = (v0 > 0.f) ? v0 : LRELU * v0;
                v1 = (v1 > 0.f) ? v1 : LRELU * v1;
                v2 = (v2 > 0.f) ? v2 : LRELU * v2;
                v3 = (v3 > 0.f) ? v3 : LRELU * v3;
            }
            if (OUT_HALF) {
                __half* C = (__half*)CoutV;
                *(__half2*)(C + (size_t)rrow * Nout + col) = __floats2half2_rn(v0, v1);
                *(__half2*)(C + (size_t)(rrow + 8) * Nout + col) = __floats2half2_rn(v2, v3);
            } else {
                float* C = (float*)CoutV;
                *(float2*)(C + (size_t)rrow * Nout + col) = make_float2(v0, v1);
                *(float2*)(C + (size_t)(rrow + 8) * Nout + col) = make_float2(v2, v3);
            }
        }
    }
}

// ---------------- launch ----------------
extern "C" void kernel_launch(void* const* d_in, const int* in_sizes, int n_in,
                              void* d_out, int out_size) {
    const float* mhs  = (const float*)d_in[0];
    const float* ehs  = (const float*)d_in[1];
    const float* shs  = (const float*)d_in[2];
    const int*   esrc = (const int*)d_in[3];
    const int*   edst = (const int*)d_in[4];
    const float* temb = (const float*)d_in[5];
    const float* lns  = (const float*)d_in[6];
    const float* lnb  = (const float*)d_in[7];
    const float* gw   = (const float*)d_in[8];
    const float* gb   = (const float*)d_in[9];
    const float* fcw  = (const float*)d_in[10];
    const float* fcb  = (const float*)d_in[11];
    float* out = (float*)d_out;

    cudaFuncSetAttribute(mma_gemm_kernel<true>,
                         cudaFuncAttributeMaxDynamicSharedMemorySize, GEMM_SMEM);
    cudaFuncSetAttribute(mma_gemm_kernel<false>,
                         cudaFuncAttributeMaxDynamicSharedMemorySize, GEMM_SMEM);

    __half *wt, *fcw_h, *ah, *xh;
    cudaGetSymbolAddress((void**)&wt,    g_wt);
    cudaGetSymbolAddress((void**)&fcw_h, g_fcw);
    cudaGetSymbolAddress((void**)&ah,    g_ah);
    cudaGetSymbolAddress((void**)&xh,    g_xh);

    fused_prep_kernel<<<NNODES + ZBLKS + TBLKS, 256>>>(mhs, ehs, shs, temb, lns, lnb, gw, fcw);
    degree_kernel<<<(NEDGE + 255) / 256, 256>>>(esrc, edst);
    scan_dinv_kernel<<<1, 1024>>>();
    fill_csr_kernel<<<(NEDGE + 255) / 256, 256>>>(esrc, edst);

    // layers 1-2: full node set
    for (int l = 0; l < NLAYER - 1; l++) {
        aggregate_kernel<false><<<NNODES, 256>>>();
        mma_gemm_kernel<true><<<dim3(DDIM / 128, NNODES / 128), 256, GEMM_SMEM>>>(
            ah, wt + (size_t)l * DDIM * DDIM, gb + (size_t)l * DDIM, xh, DDIM, /*relu=*/1);
    }

    // layer 3: entity dst rows only (compact M = 6400); output compact into g_xh
    aggregate_kernel<true><<<NENT, 256>>>();
    mma_gemm_kernel<true><<<dim3(DDIM / 128, NENT / 128), 256, GEMM_SMEM>>>(
        ah, wt + (size_t)2 * DDIM * DDIM, gb + (size_t)2 * DDIM, xh, DDIM, /*relu=*/1);

    // fc on compact entity rows
    mma_gemm_kernel<false><<<dim3(OUTF / 128, NENT / 128), 256, GEMM_SMEM>>>(
        xh, fcw_h, fcb, out, OUTF, /*relu=*/0);
}